// round 2
// baseline (speedup 1.0000x reference)
#include <cuda_runtime.h>
#include <math.h>

#define NMAX 50000
#define EMAX 800000
#define CIN 64
#define COUT 128
#define TCC 512
#define NH 4
#define DHD 32

// ---------------- scratch (static device globals; no allocation allowed) ----
__device__ float    g_deg[NMAX];
__device__ float    g_dinv[NMAX];
__device__ float    g_tt[COUT];
__device__ unsigned g_fill;
__device__ float    g_a64 [NMAX * CIN];
__device__ float    g_xw  [NMAX * COUT];
__device__ float    g_h   [NMAX * COUT];
__device__ float    g_a128[NMAX * COUT];
__device__ float    g_ha  [NMAX * COUT];
__device__ float    g_als [NMAX * NH];
__device__ float    g_ald [NMAX * NH];
__device__ unsigned g_m   [NMAX * NH];
__device__ float    g_s   [NMAX * NH];
__device__ float    g_e   [EMAX * NH];

// ---------------- helpers ---------------------------------------------------
__device__ __forceinline__ float lrelu(float v, float s) { return v > 0.f ? v : s * v; }

// order-preserving float<->uint for atomicMax on signed floats
__device__ __forceinline__ unsigned encf(float f) {
    unsigned u = __float_as_uint(f);
    return (u & 0x80000000u) ? ~u : (u | 0x80000000u);
}
__device__ __forceinline__ float decf(unsigned u) {
    return (u & 0x80000000u) ? __uint_as_float(u & 0x7fffffffu) : __uint_as_float(~u);
}

// sm_90+ vector float reduction (no return value) — 1 LTS op per 16B
__device__ __forceinline__ void red4(float* p, float4 v) {
    asm volatile("red.global.add.v4.f32 [%0], {%1,%2,%3,%4};"
                 :: "l"(p), "f"(v.x), "f"(v.y), "f"(v.z), "f"(v.w) : "memory");
}

// ---------------- kernels ---------------------------------------------------

__global__ void k_init_nodes(int n) {
    int i = blockIdx.x * blockDim.x + threadIdx.x;
    if (i == 0) g_fill = 0u;            // enc(x>=0) > 0, ew ~ U[0,1)
    if (i < n) g_deg[i] = 1.0f;         // self-loop weight
}

__global__ void k_edge_prep(const int* __restrict__ col, const float* __restrict__ ew, int E) {
    int e = blockIdx.x * blockDim.x + threadIdx.x;
    float w = 0.f;
    if (e < E) { w = ew[e]; atomicAdd(&g_deg[col[e]], w); }
    // block max reduce -> 1 atomic per block (avoid 800K single-address REDs)
    #pragma unroll
    for (int off = 16; off; off >>= 1) w = fmaxf(w, __shfl_down_sync(0xffffffffu, w, off));
    __shared__ float sm[8];
    int lane = threadIdx.x & 31, wid = threadIdx.x >> 5;
    if (lane == 0) sm[wid] = w;
    __syncthreads();
    if (threadIdx.x == 0) {
        float m = sm[0];
        #pragma unroll
        for (int i = 1; i < 8; i++) m = fmaxf(m, sm[i]);
        atomicMax(&g_fill, encf(m));
    }
}

__global__ void k_dinv(int n) {
    int i = blockIdx.x * blockDim.x + threadIdx.x;
    if (i < n) g_dinv[i] = rsqrtf(g_deg[i]);   // deg >= 1 always
}

__global__ void k_tt(const float* __restrict__ t, const float* __restrict__ tew,
                     const float* __restrict__ teb) {
    int j = threadIdx.x;  // 128 threads
    float acc = teb[j];
    for (int k = 0; k < TCC; k++) acc += lrelu(t[k], 0.01f) * tew[k * COUT + j];
    g_tt[j] = acc;
}

// group norm (G=8) + LeakyReLU(0.01); one thread per (node, group)
template <int C, int GS>
__global__ void k_gn(const float* __restrict__ x, const float* __restrict__ w,
                     const float* __restrict__ b, float* __restrict__ out, int n) {
    int idx = blockIdx.x * blockDim.x + threadIdx.x;
    if (idx >= n * 8) return;
    int node = idx >> 3, g = idx & 7;
    const float* xp = x + node * C + g * GS;
    float v[GS];
    #pragma unroll
    for (int i = 0; i < GS; i += 4) {
        float4 t4 = *(const float4*)(xp + i);
        v[i] = t4.x; v[i + 1] = t4.y; v[i + 2] = t4.z; v[i + 3] = t4.w;
    }
    float s = 0.f, ss = 0.f;
    #pragma unroll
    for (int i = 0; i < GS; i++) { s += v[i]; ss += v[i] * v[i]; }
    float mean = s * (1.f / GS);
    float var  = ss * (1.f / GS) - mean * mean;
    float inv  = rsqrtf(var + 1e-5f);
    float* op = out + node * C + g * GS;
    #pragma unroll
    for (int i = 0; i < GS; i += 4) {
        float4 o;
        o.x = lrelu((v[i    ] - mean) * inv * w[g * GS + i    ] + b[g * GS + i    ], 0.01f);
        o.y = lrelu((v[i + 1] - mean) * inv * w[g * GS + i + 1] + b[g * GS + i + 1], 0.01f);
        o.z = lrelu((v[i + 2] - mean) * inv * w[g * GS + i + 2] + b[g * GS + i + 2], 0.01f);
        o.w = lrelu((v[i + 3] - mean) * inv * w[g * GS + i + 3] + b[g * GS + i + 3], 0.01f);
        *(float4*)(op + i) = o;
    }
}

// [n,K] @ [K,128] tiled SGEMM. 128 threads (1 col each), 32 rows/block.
// EPI=1: out = acc + bias[j] + dinv[r]^2 * selfbuf[r*128+j]  (residual + GCN self-loop)
template <int K, int EPI>
__global__ void k_mm(const float* __restrict__ A, const float* __restrict__ W,
                     float* __restrict__ out, int n,
                     const float* __restrict__ bias, const float* __restrict__ selfbuf) {
    const int ROWS = 32;
    __shared__ float sW[64 * 128];
    __shared__ float sA[ROWS * 64];
    int j  = threadIdx.x;
    int r0 = blockIdx.x * ROWS;
    float acc[ROWS];
    #pragma unroll
    for (int r = 0; r < ROWS; r++) acc[r] = 0.f;

    for (int k0 = 0; k0 < K; k0 += 64) {
        __syncthreads();
        for (int i = j; i < 64 * 128; i += 128) sW[i] = W[k0 * 128 + i];
        for (int i = j; i < ROWS * 64; i += 128) {
            int r = i >> 6, k = i & 63;
            int rr = r0 + r;
            sA[i] = (rr < n) ? A[rr * K + k0 + k] : 0.f;
        }
        __syncthreads();
        #pragma unroll 4
        for (int k = 0; k < 64; k++) {
            float wv = sW[k * 128 + j];
            #pragma unroll
            for (int r = 0; r < ROWS; r++) acc[r] += sA[r * 64 + k] * wv;
        }
    }
    #pragma unroll
    for (int r = 0; r < ROWS; r++) {
        int rr = r0 + r;
        if (rr < n) {
            float v = acc[r];
            if (EPI == 1) {
                float d = g_dinv[rr];
                v += bias[j] + d * d * selfbuf[rr * 128 + j];
            }
            out[rr * 128 + j] = v;
        }
    }
}

// h = b1 + tt + dinv^2 * xw1  (bias + time-embed + GCN self-loop)
__global__ void k_init_h(const float* __restrict__ b1, int n) {
    int idx = blockIdx.x * blockDim.x + threadIdx.x;
    if (idx >= n * COUT) return;
    int node = idx >> 7, c = idx & 127;
    float d = g_dinv[node];
    g_h[idx] = b1[c] + g_tt[c] + d * d * g_xw[idx];
}

// GCN edge scatter: warp per edge, coalesced 512B gather + red.v4 scatter
__global__ void k_scatter(const float* __restrict__ src, float* __restrict__ dst,
                          const int* __restrict__ row, const int* __restrict__ col,
                          const float* __restrict__ ew, int E) {
    int gid = blockIdx.x * blockDim.x + threadIdx.x;
    int e = gid >> 5, lane = gid & 31;
    if (e >= E) return;
    int r = __ldg(row + e), c = __ldg(col + e);
    float coef = g_dinv[r] * __ldg(ew + e) * g_dinv[c];
    float4 v = *(const float4*)(src + r * COUT + lane * 4);
    v.x *= coef; v.y *= coef; v.z *= coef; v.w *= coef;
    red4(dst + c * COUT + lane * 4, v);
}

// attention logits: per-node src/dst projections
__global__ void k_al(const float* __restrict__ asrc, const float* __restrict__ adst, int n) {
    int idx = blockIdx.x * blockDim.x + threadIdx.x;
    if (idx >= n * NH) return;
    int node = idx >> 2, h = idx & 3;
    const float* hp = g_ha + node * COUT + h * DHD;
    float ds = 0.f, dd = 0.f;
    #pragma unroll
    for (int d = 0; d < DHD; d++) {
        float v = hp[d];
        ds += v * __ldg(asrc + h * DHD + d);
        dd += v * __ldg(adst + h * DHD + d);
    }
    g_als[idx] = ds;
    g_ald[idx] = dd;
}

__device__ __forceinline__ float self_logit(int node, int h, const float* aedge) {
    float fillv = decf(g_fill);
    return lrelu(g_als[node * 4 + h] + g_ald[node * 4 + h] + __ldg(aedge + h) * fillv, 0.2f);
}

// init segment-max with self-loop logit
__global__ void k_init_m(const float* __restrict__ aedge, int n) {
    int idx = blockIdx.x * blockDim.x + threadIdx.x;
    if (idx >= n * NH) return;
    g_m[idx] = encf(self_logit(idx >> 2, idx & 3, aedge));
}

__global__ void k_att_max(const int* __restrict__ row, const int* __restrict__ col,
                          const float* __restrict__ ew, const float* __restrict__ aedge, int E) {
    int e = blockIdx.x * blockDim.x + threadIdx.x;
    if (e >= E) return;
    int r = row[e], c = col[e];
    float w = ew[e];
    float4 as = *(const float4*)(g_als + r * 4);
    float4 ad = *(const float4*)(g_ald + c * 4);
    float4 ae = *(const float4*)aedge;
    unsigned* mp = g_m + c * 4;
    atomicMax(mp + 0, encf(lrelu(as.x + ad.x + ae.x * w, 0.2f)));
    atomicMax(mp + 1, encf(lrelu(as.y + ad.y + ae.y * w, 0.2f)));
    atomicMax(mp + 2, encf(lrelu(as.z + ad.z + ae.z * w, 0.2f)));
    atomicMax(mp + 3, encf(lrelu(as.w + ad.w + ae.w * w, 0.2f)));
}

// init segment-sum with self-loop exp term
__global__ void k_init_s(const float* __restrict__ aedge, int n) {
    int idx = blockIdx.x * blockDim.x + threadIdx.x;
    if (idx >= n * NH) return;
    float sl = self_logit(idx >> 2, idx & 3, aedge);
    g_s[idx] = expf(sl - decf(g_m[idx]));
}

__global__ void k_att_exp(const int* __restrict__ row, const int* __restrict__ col,
                          const float* __restrict__ ew, const float* __restrict__ aedge, int E) {
    int e = blockIdx.x * blockDim.x + threadIdx.x;
    if (e >= E) return;
    int r = row[e], c = col[e];
    float w = ew[e];
    float4 as = *(const float4*)(g_als + r * 4);
    float4 ad = *(const float4*)(g_ald + c * 4);
    float4 ae = *(const float4*)aedge;
    float4 ev;
    ev.x = expf(lrelu(as.x + ad.x + ae.x * w, 0.2f) - decf(g_m[c * 4 + 0]));
    ev.y = expf(lrelu(as.y + ad.y + ae.y * w, 0.2f) - decf(g_m[c * 4 + 1]));
    ev.z = expf(lrelu(as.z + ad.z + ae.z * w, 0.2f) - decf(g_m[c * 4 + 2]));
    ev.w = expf(lrelu(as.w + ad.w + ae.w * w, 0.2f) - decf(g_m[c * 4 + 3]));
    *(float4*)(g_e + e * 4) = ev;
    red4(g_s + c * 4, ev);
}

// out = ba + alpha_self * ha  (self-loop term of the attention aggregation)
__global__ void k_out_init(float* __restrict__ out, const float* __restrict__ ba,
                           const float* __restrict__ aedge, int n) {
    int idx = blockIdx.x * blockDim.x + threadIdx.x;
    if (idx >= n * COUT) return;
    int node = idx >> 7, ch = idx & 127, h = ch >> 5;
    float sl = self_logit(node, h, aedge);
    float alpha = expf(sl - decf(g_m[node * 4 + h])) / (g_s[node * 4 + h] + 1e-16f);
    out[idx] = ba[ch] + alpha * g_ha[idx];
}

__global__ void k_att_scatter(float* __restrict__ out, const int* __restrict__ row,
                              const int* __restrict__ col, int E) {
    int gid = blockIdx.x * blockDim.x + threadIdx.x;
    int e = gid >> 5, lane = gid & 31;
    if (e >= E) return;
    int r = __ldg(row + e), c = __ldg(col + e);
    int h = lane >> 3;                         // 8 lanes per head (32 floats)
    float alpha = __ldg(g_e + e * 4 + h) / (g_s[c * 4 + h] + 1e-16f);
    float4 v = *(const float4*)(g_ha + r * COUT + lane * 4);
    v.x *= alpha; v.y *= alpha; v.z *= alpha; v.w *= alpha;
    red4(out + c * COUT + lane * 4, v);
}

// ---------------- launch ----------------------------------------------------
extern "C" void kernel_launch(void* const* d_in, const int* in_sizes, int n_in,
                              void* d_out, int out_size) {
    const float* x    = (const float*)d_in[0];
    const float* t    = (const float*)d_in[1];
    const int*   ei   = (const int*)  d_in[2];
    const float* ew   = (const float*)d_in[3];
    const float* gn0w = (const float*)d_in[4];
    const float* gn0b = (const float*)d_in[5];
    const float* W1   = (const float*)d_in[6];
    const float* b1   = (const float*)d_in[7];
    const float* gn1w = (const float*)d_in[8];
    const float* gn1b = (const float*)d_in[9];
    const float* W2   = (const float*)d_in[10];
    const float* b2   = (const float*)d_in[11];
    const float* Wres = (const float*)d_in[12];
    const float* tew  = (const float*)d_in[13];
    const float* teb  = (const float*)d_in[14];
    const float* gn2w = (const float*)d_in[15];
    const float* gn2b = (const float*)d_in[16];
    const float* Wa   = (const float*)d_in[17];
    const float* asrc = (const float*)d_in[18];
    const float* adst = (const float*)d_in[19];
    const float* aedg = (const float*)d_in[20];
    const float* ba   = (const float*)d_in[21];

    int n = in_sizes[0] / CIN;
    int E = in_sizes[3];
    const int* row  = ei;
    const int* colp = ei + E;
    float* out = (float*)d_out;

    float *p_a64, *p_xw, *p_h, *p_a128, *p_ha;
    cudaGetSymbolAddress((void**)&p_a64,  g_a64);
    cudaGetSymbolAddress((void**)&p_xw,   g_xw);
    cudaGetSymbolAddress((void**)&p_h,    g_h);
    cudaGetSymbolAddress((void**)&p_a128, g_a128);
    cudaGetSymbolAddress((void**)&p_ha,   g_ha);

    const int T = 256;
    int gN    = (n + T - 1) / T;
    int gE    = (E + T - 1) / T;
    int gNG   = (n * 8 + T - 1) / T;
    int gNC   = (n * COUT + T - 1) / T;
    int gNH_  = (n * NH + T - 1) / T;
    int gEW   = (E * 32 + T - 1) / T;   // warp-per-edge
    int gMM   = (n + 31) / 32;

    // ---- degree / norm / time-embed ----
    k_init_nodes<<<gN, T>>>(n);
    k_edge_prep<<<gE, T>>>(colp, ew, E);
    k_dinv<<<gN, T>>>(n);
    k_tt<<<1, 128>>>(t, tew, teb);

    // ---- ResBlock layer 1 ----
    k_gn<CIN, 8><<<gNG, T>>>(x, gn0w, gn0b, p_a64, n);
    k_mm<CIN, 0><<<gMM, 128>>>(p_a64, W1, p_xw, n, nullptr, nullptr);
    k_init_h<<<gNC, T>>>(b1, n);
    k_scatter<<<gEW, T>>>(p_xw, p_h, row, colp, ew, E);

    // ---- ResBlock layer 2 + residual ----
    k_gn<COUT, 16><<<gNG, T>>>(p_h, gn1w, gn1b, p_a128, n);
    k_mm<COUT, 0><<<gMM, 128>>>(p_a128, W2, p_xw, n, nullptr, nullptr);
    k_mm<CIN, 1><<<gMM, 128>>>(x, Wres, p_h, n, b2, p_xw);   // h2 = x@Wres + b2 + self
    k_scatter<<<gEW, T>>>(p_xw, p_h, row, colp, ew, E);

    // ---- AttnBlock (GAT) ----
    k_gn<COUT, 16><<<gNG, T>>>(p_h, gn2w, gn2b, p_a128, n);
    k_mm<COUT, 0><<<gMM, 128>>>(p_a128, Wa, p_ha, n, nullptr, nullptr);
    k_al<<<gNH_, T>>>(asrc, adst, n);
    k_init_m<<<gNH_, T>>>(aedg, n);
    k_att_max<<<gE, T>>>(row, colp, ew, aedg, E);
    k_init_s<<<gNH_, T>>>(aedg, n);
    k_att_exp<<<gE, T>>>(row, colp, ew, aedg, E);
    k_out_init<<<gNC, T>>>(out, ba, aedg, n);
    k_att_scatter<<<gEW, T>>>(out, row, colp, E);
}

// round 3
// speedup vs baseline: 2.2872x; 2.2872x over previous
#include <cuda_runtime.h>
#include <math.h>

#define NMAX 50000
#define EMAX 800000
#define CIN 64
#define COUT 128
#define TCC 512
#define NH 4

// ---------------- scratch ----------------------------------------------------
__device__ float    g_deg[NMAX];
__device__ float    g_dinv[NMAX];
__device__ float    g_btt[COUT];         // b1 + time-embed vector
__device__ unsigned g_fill;
__device__ int      g_count[NMAX];
__device__ int      g_ptr[NMAX + 1];
__device__ int      g_cursor[NMAX];
__device__ int      g_part[256];
__device__ int      g_pscan[256];
__device__ int      g_csr_r[EMAX];
__device__ float    g_csr_w[EMAX];
__device__ float    g_a64 [NMAX * CIN];
__device__ float    g_xw  [NMAX * COUT];
__device__ float    g_h   [NMAX * COUT];
__device__ float    g_a128[NMAX * COUT];
__device__ float    g_ha  [NMAX * COUT];
__device__ float    g_als [NMAX * NH];
__device__ float    g_ald [NMAX * NH];

// ---------------- helpers ----------------------------------------------------
__device__ __forceinline__ float lrelu(float v, float s) { return v > 0.f ? v : s * v; }
__device__ __forceinline__ unsigned encf(float f) {
    unsigned u = __float_as_uint(f);
    return (u & 0x80000000u) ? ~u : (u | 0x80000000u);
}
__device__ __forceinline__ float decf(unsigned u) {
    return (u & 0x80000000u) ? __uint_as_float(u & 0x7fffffffu) : __uint_as_float(~u);
}

// ---------------- setup kernels ----------------------------------------------
__global__ void k_init(const float* __restrict__ teb, const float* __restrict__ b1, int n) {
    int i = blockIdx.x * blockDim.x + threadIdx.x;
    if (i == 0) g_fill = 0u;
    if (i < COUT) g_btt[i] = teb[i] + b1[i];
    if (i < n) { g_deg[i] = 1.0f; g_count[i] = 0; }
}

__global__ void k_count(const int* __restrict__ col, const float* __restrict__ ew, int E) {
    int e = blockIdx.x * blockDim.x + threadIdx.x;
    float w = 0.f;
    if (e < E) {
        w = ew[e];
        int c = col[e];
        atomicAdd(&g_count[c], 1);
        atomicAdd(&g_deg[c], w);
    }
    #pragma unroll
    for (int off = 16; off; off >>= 1) w = fmaxf(w, __shfl_down_sync(0xffffffffu, w, off));
    __shared__ float sm[8];
    int lane = threadIdx.x & 31, wid = threadIdx.x >> 5;
    if (lane == 0) sm[wid] = w;
    __syncthreads();
    if (threadIdx.x == 0) {
        float m = sm[0];
        #pragma unroll
        for (int i = 1; i < 8; i++) m = fmaxf(m, sm[i]);
        atomicMax(&g_fill, encf(m));
    }
}

__global__ void kScan1(int n1) {          // inclusive block scan -> exclusive ptr + block totals
    __shared__ int sm[256];
    int tid = threadIdx.x;
    int i = blockIdx.x * 256 + tid;
    int x = (i < n1 - 1) ? g_count[i] : 0;
    sm[tid] = x;
    __syncthreads();
    #pragma unroll
    for (int off = 1; off < 256; off <<= 1) {
        int v = (tid >= off) ? sm[tid - off] : 0;
        __syncthreads();
        sm[tid] += v;
        __syncthreads();
    }
    if (i < n1) g_ptr[i] = sm[tid] - x;
    if (tid == 255) g_part[blockIdx.x] = sm[255];
}

__global__ void kScan2(int nb) {          // single block, exclusive scan of partials
    __shared__ int sm[256];
    int tid = threadIdx.x;
    int x = (tid < nb) ? g_part[tid] : 0;
    sm[tid] = x;
    __syncthreads();
    #pragma unroll
    for (int off = 1; off < 256; off <<= 1) {
        int v = (tid >= off) ? sm[tid - off] : 0;
        __syncthreads();
        sm[tid] += v;
        __syncthreads();
    }
    g_pscan[tid] = sm[tid] - x;
}

__global__ void kScan3(int n1) {
    int i = blockIdx.x * blockDim.x + threadIdx.x;
    if (i < n1) {
        int v = g_ptr[i] + g_pscan[i >> 8];
        g_ptr[i] = v;
        if (i < n1 - 1) g_cursor[i] = v;
    }
}

__global__ void k_place(const int* __restrict__ row, const int* __restrict__ col,
                        const float* __restrict__ ew, int E) {
    int e = blockIdx.x * blockDim.x + threadIdx.x;
    if (e >= E) return;
    int c = col[e];
    int slot = atomicAdd(&g_cursor[c], 1);
    g_csr_r[slot] = row[e];
    g_csr_w[slot] = ew[e];
}

__global__ void k_dinv(int n) {
    int i = blockIdx.x * blockDim.x + threadIdx.x;
    if (i < n) g_dinv[i] = rsqrtf(g_deg[i]);
}

__global__ void k_tt_partial(const float* __restrict__ t, const float* __restrict__ tew) {
    int j = threadIdx.x;                  // 128 threads, 32 blocks of 16 k's
    int k0 = blockIdx.x * 16;
    float acc = 0.f;
    #pragma unroll
    for (int k = 0; k < 16; k++) acc += lrelu(t[k0 + k], 0.01f) * tew[(k0 + k) * COUT + j];
    atomicAdd(&g_btt[j], acc);
}

// ---------------- group norm + LeakyReLU(0.01) -------------------------------
template <int C, int GS>
__global__ void k_gn(const float* __restrict__ x, const float* __restrict__ w,
                     const float* __restrict__ b, float* __restrict__ out, int n) {
    int idx = blockIdx.x * blockDim.x + threadIdx.x;
    if (idx >= n * 8) return;
    int node = idx >> 3, g = idx & 7;
    const float* xp = x + (size_t)node * C + g * GS;
    float v[GS];
    #pragma unroll
    for (int i = 0; i < GS; i += 4) {
        float4 t4 = *(const float4*)(xp + i);
        v[i] = t4.x; v[i + 1] = t4.y; v[i + 2] = t4.z; v[i + 3] = t4.w;
    }
    float s = 0.f, ss = 0.f;
    #pragma unroll
    for (int i = 0; i < GS; i++) { s += v[i]; ss += v[i] * v[i]; }
    float mean = s * (1.f / GS);
    float var  = ss * (1.f / GS) - mean * mean;
    float inv  = rsqrtf(var + 1e-5f);
    float* op = out + (size_t)node * C + g * GS;
    #pragma unroll
    for (int i = 0; i < GS; i += 4) {
        float4 o;
        o.x = lrelu((v[i    ] - mean) * inv * w[g * GS + i    ] + b[g * GS + i    ], 0.01f);
        o.y = lrelu((v[i + 1] - mean) * inv * w[g * GS + i + 1] + b[g * GS + i + 1], 0.01f);
        o.z = lrelu((v[i + 2] - mean) * inv * w[g * GS + i + 2] + b[g * GS + i + 2], 0.01f);
        o.w = lrelu((v[i + 3] - mean) * inv * w[g * GS + i + 3] + b[g * GS + i + 3], 0.01f);
        *(float4*)(op + i) = o;
    }
}

// ---------------- register-tiled SGEMM: [n,K] @ [K,128] ----------------------
// BM=128, BN=128, BK=8, 256 threads, 8x8 per thread. BIAS=1 adds bias[j].
template <int K, int BIAS>
__global__ __launch_bounds__(256)
void k_gemm(const float* __restrict__ A, const float* __restrict__ W,
            const float* __restrict__ bias, float* __restrict__ out, int n) {
    __shared__ float As[8][128];
    __shared__ float Bs[8][128];
    int tid = threadIdx.x;
    int m0 = blockIdx.x * 128;
    int tx = tid & 15, ty = tid >> 4;
    int lm = tid >> 1, lh = (tid & 1) * 4;     // A-load: row lm, k-offset lh
    int bk = tid >> 5, bc = (tid & 31) * 4;    // B-load: k-row bk, col bc
    float acc[8][8];
    #pragma unroll
    for (int i = 0; i < 8; i++)
        #pragma unroll
        for (int j = 0; j < 8; j++) acc[i][j] = 0.f;

    for (int k0 = 0; k0 < K; k0 += 8) {
        float4 av = make_float4(0.f, 0.f, 0.f, 0.f);
        if (m0 + lm < n) av = *(const float4*)(A + (size_t)(m0 + lm) * K + k0 + lh);
        As[lh + 0][lm] = av.x; As[lh + 1][lm] = av.y;
        As[lh + 2][lm] = av.z; As[lh + 3][lm] = av.w;
        *(float4*)(&Bs[bk][bc]) = *(const float4*)(W + (size_t)(k0 + bk) * 128 + bc);
        __syncthreads();
        #pragma unroll
        for (int k = 0; k < 8; k++) {
            float4 a0 = *(const float4*)(&As[k][ty * 8]);
            float4 a1 = *(const float4*)(&As[k][ty * 8 + 4]);
            float4 b0 = *(const float4*)(&Bs[k][tx * 4]);
            float4 b1 = *(const float4*)(&Bs[k][64 + tx * 4]);
            float am[8] = {a0.x, a0.y, a0.z, a0.w, a1.x, a1.y, a1.z, a1.w};
            float bn[8] = {b0.x, b0.y, b0.z, b0.w, b1.x, b1.y, b1.z, b1.w};
            #pragma unroll
            for (int mi = 0; mi < 8; mi++)
                #pragma unroll
                for (int ni = 0; ni < 8; ni++) acc[mi][ni] += am[mi] * bn[ni];
        }
        __syncthreads();
    }
    #pragma unroll
    for (int mi = 0; mi < 8; mi++) {
        int m = m0 + ty * 8 + mi;
        if (m < n) {
            #pragma unroll
            for (int half = 0; half < 2; half++) {
                int colb = half * 64 + tx * 4;
                float4 o;
                o.x = acc[mi][half * 4 + 0]; o.y = acc[mi][half * 4 + 1];
                o.z = acc[mi][half * 4 + 2]; o.w = acc[mi][half * 4 + 3];
                if (BIAS) {
                    float4 bb = *(const float4*)(bias + colb);
                    o.x += bb.x; o.y += bb.y; o.z += bb.z; o.w += bb.w;
                }
                *(float4*)(out + (size_t)m * 128 + colb) = o;
            }
        }
    }
}

// ---------------- GCN conv: warp-per-node CSR gather -------------------------
// dst[c] = base + dinv[c]^2 * src[c] + sum_e dinv[r]*w*dinv[c] * src[r]
// BASEVEC=1: base = g_btt[channel]; else base = basep[c*128+ch]
template <int BASEVEC>
__global__ void k_conv(const float* __restrict__ src, const float* __restrict__ basep,
                       float* __restrict__ dst, int n) {
    int gw = (blockIdx.x * blockDim.x + threadIdx.x) >> 5;
    int lane = threadIdx.x & 31;
    if (gw >= n) return;
    int c = gw;
    int beg = g_ptr[c], end = g_ptr[c + 1];
    float dc = g_dinv[c];
    float4 base = BASEVEC ? *(const float4*)(g_btt + lane * 4)
                          : *(const float4*)(basep + (size_t)c * 128 + lane * 4);
    float4 sc = *(const float4*)(src + (size_t)c * 128 + lane * 4);
    float d2 = dc * dc;
    float4 acc;
    acc.x = base.x + d2 * sc.x; acc.y = base.y + d2 * sc.y;
    acc.z = base.z + d2 * sc.z; acc.w = base.w + d2 * sc.w;
    #pragma unroll 2
    for (int i = beg; i < end; i++) {
        int r = g_csr_r[i];
        float w = g_csr_w[i];
        float coef = g_dinv[r] * w * dc;
        float4 v = *(const float4*)(src + (size_t)r * 128 + lane * 4);
        acc.x += coef * v.x; acc.y += coef * v.y;
        acc.z += coef * v.z; acc.w += coef * v.w;
    }
    *(float4*)(dst + (size_t)c * 128 + lane * 4) = acc;
}

// ---------------- attention projections --------------------------------------
__global__ void k_al(const float* __restrict__ asrc, const float* __restrict__ adst, int n) {
    int idx = blockIdx.x * blockDim.x + threadIdx.x;
    if (idx >= n * NH) return;
    int node = idx >> 2, h = idx & 3;
    const float4* hp = (const float4*)(g_ha + (size_t)node * COUT + h * 32);
    const float4* sp = (const float4*)(asrc + h * 32);
    const float4* dp = (const float4*)(adst + h * 32);
    float ds = 0.f, dd = 0.f;
    #pragma unroll
    for (int i = 0; i < 8; i++) {
        float4 v = hp[i], a = sp[i], b = dp[i];
        ds += v.x * a.x + v.y * a.y + v.z * a.z + v.w * a.w;
        dd += v.x * b.x + v.y * b.y + v.z * b.z + v.w * b.w;
    }
    g_als[idx] = ds;
    g_ald[idx] = dd;
}

// ---------------- fused GAT: warp-per-node, no atomics -----------------------
__global__ __launch_bounds__(256)
void k_attn(const float* __restrict__ aedge, const float* __restrict__ ba,
            float* __restrict__ out, int n) {
    __shared__ float s_e[8][256];       // 64 edges x 4 heads per warp
    int gw = (blockIdx.x * blockDim.x + threadIdx.x) >> 5;
    int lane = threadIdx.x & 31;
    int wl = threadIdx.x >> 5;
    if (gw >= n) return;
    int c = gw;
    int beg = g_ptr[c], end = g_ptr[c + 1];
    float4 ae = *(const float4*)aedge;
    float4 ad = *(const float4*)(g_ald + c * 4);
    float4 asc = *(const float4*)(g_als + c * 4);
    float fill = decf(g_fill);
    // self logits
    float l0 = lrelu(asc.x + ad.x + ae.x * fill, 0.2f);
    float l1 = lrelu(asc.y + ad.y + ae.y * fill, 0.2f);
    float l2 = lrelu(asc.z + ad.z + ae.z * fill, 0.2f);
    float l3 = lrelu(asc.w + ad.w + ae.w * fill, 0.2f);
    float m0 = l0, m1 = l1, m2 = l2, m3 = l3;
    // phase A: max (lane-strided)
    for (int i = beg + lane; i < end; i += 32) {
        int r = g_csr_r[i];
        float w = g_csr_w[i];
        float4 as = *(const float4*)(g_als + r * 4);
        m0 = fmaxf(m0, lrelu(as.x + ad.x + ae.x * w, 0.2f));
        m1 = fmaxf(m1, lrelu(as.y + ad.y + ae.y * w, 0.2f));
        m2 = fmaxf(m2, lrelu(as.z + ad.z + ae.z * w, 0.2f));
        m3 = fmaxf(m3, lrelu(as.w + ad.w + ae.w * w, 0.2f));
    }
    #pragma unroll
    for (int off = 16; off; off >>= 1) {
        m0 = fmaxf(m0, __shfl_xor_sync(0xffffffffu, m0, off));
        m1 = fmaxf(m1, __shfl_xor_sync(0xffffffffu, m1, off));
        m2 = fmaxf(m2, __shfl_xor_sync(0xffffffffu, m2, off));
        m3 = fmaxf(m3, __shfl_xor_sync(0xffffffffu, m3, off));
    }
    // phase B: exp + sum (cache e-values in smem)
    float s0 = 0.f, s1 = 0.f, s2 = 0.f, s3 = 0.f;
    for (int i = beg + lane; i < end; i += 32) {
        int r = g_csr_r[i];
        float w = g_csr_w[i];
        float4 as = *(const float4*)(g_als + r * 4);
        float e0 = __expf(lrelu(as.x + ad.x + ae.x * w, 0.2f) - m0);
        float e1 = __expf(lrelu(as.y + ad.y + ae.y * w, 0.2f) - m1);
        float e2 = __expf(lrelu(as.z + ad.z + ae.z * w, 0.2f) - m2);
        float e3 = __expf(lrelu(as.w + ad.w + ae.w * w, 0.2f) - m3);
        int il = i - beg;
        if (il < 64) {
            float4 ev = make_float4(e0, e1, e2, e3);
            *(float4*)(&s_e[wl][il * 4]) = ev;
        }
        s0 += e0; s1 += e1; s2 += e2; s3 += e3;
    }
    #pragma unroll
    for (int off = 16; off; off >>= 1) {
        s0 += __shfl_xor_sync(0xffffffffu, s0, off);
        s1 += __shfl_xor_sync(0xffffffffu, s1, off);
        s2 += __shfl_xor_sync(0xffffffffu, s2, off);
        s3 += __shfl_xor_sync(0xffffffffu, s3, off);
    }
    float e0s = __expf(l0 - m0), e1s = __expf(l1 - m1);
    float e2s = __expf(l2 - m2), e3s = __expf(l3 - m3);
    s0 += e0s; s1 += e1s; s2 += e2s; s3 += e3s;
    float rs0 = 1.f / (s0 + 1e-16f), rs1 = 1.f / (s1 + 1e-16f);
    float rs2 = 1.f / (s2 + 1e-16f), rs3 = 1.f / (s3 + 1e-16f);
    __syncwarp();
    // phase C: weighted aggregation (whole warp per edge)
    int h = lane >> 3;
    float rs  = (h == 0) ? rs0 : (h == 1) ? rs1 : (h == 2) ? rs2 : rs3;
    float mh  = (h == 0) ? m0  : (h == 1) ? m1  : (h == 2) ? m2  : m3;
    float esf = (h == 0) ? e0s : (h == 1) ? e1s : (h == 2) ? e2s : e3s;
    float aeh = (h == 0) ? ae.x : (h == 1) ? ae.y : (h == 2) ? ae.z : ae.w;
    float adh = (h == 0) ? ad.x : (h == 1) ? ad.y : (h == 2) ? ad.z : ad.w;
    float4 acc = *(const float4*)(ba + lane * 4);
    {
        float a_self = esf * rs;
        float4 vc = *(const float4*)(g_ha + (size_t)c * 128 + lane * 4);
        acc.x += a_self * vc.x; acc.y += a_self * vc.y;
        acc.z += a_self * vc.z; acc.w += a_self * vc.w;
    }
    for (int i = beg; i < end; i++) {
        int il = i - beg;
        int r = g_csr_r[i];
        float e;
        if (il < 64) {
            e = s_e[wl][il * 4 + h];
        } else {
            float w = g_csr_w[i];
            float asl = g_als[r * 4 + h];
            e = __expf(lrelu(asl + adh + aeh * w, 0.2f) - mh);
        }
        float alpha = e * rs;
        float4 v = *(const float4*)(g_ha + (size_t)r * 128 + lane * 4);
        acc.x += alpha * v.x; acc.y += alpha * v.y;
        acc.z += alpha * v.z; acc.w += alpha * v.w;
    }
    *(float4*)(out + (size_t)c * 128 + lane * 4) = acc;
}

// ---------------- launch -----------------------------------------------------
extern "C" void kernel_launch(void* const* d_in, const int* in_sizes, int n_in,
                              void* d_out, int out_size) {
    const float* x    = (const float*)d_in[0];
    const float* t    = (const float*)d_in[1];
    const int*   ei   = (const int*)  d_in[2];
    const float* ew   = (const float*)d_in[3];
    const float* gn0w = (const float*)d_in[4];
    const float* gn0b = (const float*)d_in[5];
    const float* W1   = (const float*)d_in[6];
    const float* b1   = (const float*)d_in[7];
    const float* gn1w = (const float*)d_in[8];
    const float* gn1b = (const float*)d_in[9];
    const float* W2   = (const float*)d_in[10];
    const float* b2   = (const float*)d_in[11];
    const float* Wres = (const float*)d_in[12];
    const float* tew  = (const float*)d_in[13];
    const float* teb  = (const float*)d_in[14];
    const float* gn2w = (const float*)d_in[15];
    const float* gn2b = (const float*)d_in[16];
    const float* Wa   = (const float*)d_in[17];
    const float* asrc = (const float*)d_in[18];
    const float* adst = (const float*)d_in[19];
    const float* aedg = (const float*)d_in[20];
    const float* ba   = (const float*)d_in[21];

    int n = in_sizes[0] / CIN;
    int E = in_sizes[3];
    const int* row  = ei;
    const int* colp = ei + E;
    float* out = (float*)d_out;

    float *p_a64, *p_xw, *p_h, *p_a128, *p_ha;
    cudaGetSymbolAddress((void**)&p_a64,  g_a64);
    cudaGetSymbolAddress((void**)&p_xw,   g_xw);
    cudaGetSymbolAddress((void**)&p_h,    g_h);
    cudaGetSymbolAddress((void**)&p_a128, g_a128);
    cudaGetSymbolAddress((void**)&p_ha,   g_ha);

    const int T = 256;
    int n1   = n + 1;
    int gN   = (n + T - 1) / T;
    int gE   = (E + T - 1) / T;
    int gNG  = (n * 8 + T - 1) / T;
    int gNH_ = (n * NH + T - 1) / T;
    int gNW  = (n * 32 + T - 1) / T;        // warp-per-node kernels
    int gSC  = (n1 + 255) / 256;
    int gMM  = (n + 127) / 128;

    // ---- CSR build + degree + time embed ----
    k_init<<<gN, T>>>(teb, b1, n);
    k_count<<<gE, T>>>(colp, ew, E);
    kScan1<<<gSC, 256>>>(n1);
    kScan2<<<1, 256>>>(gSC);
    kScan3<<<gSC, 256>>>(n1);
    k_place<<<gE, T>>>(row, colp, ew, E);
    k_dinv<<<gN, T>>>(n);
    k_tt_partial<<<32, 128>>>(t, tew);

    // ---- ResBlock layer 1 ----
    k_gn<CIN, 8><<<gNG, T>>>(x, gn0w, gn0b, p_a64, n);
    k_gemm<CIN, 0><<<gMM, 256>>>(p_a64, W1, nullptr, p_xw, n);
    k_conv<1><<<gNW, T>>>(p_xw, nullptr, p_h, n);

    // ---- ResBlock layer 2 + residual ----
    k_gn<COUT, 16><<<gNG, T>>>(p_h, gn1w, gn1b, p_a128, n);
    k_gemm<COUT, 0><<<gMM, 256>>>(p_a128, W2, nullptr, p_xw, n);
    k_gemm<CIN, 1><<<gMM, 256>>>(x, Wres, b2, p_a128, n);   // base = x@Wres + b2
    k_conv<0><<<gNW, T>>>(p_xw, p_a128, p_h, n);

    // ---- AttnBlock (GAT) ----
    k_gn<COUT, 16><<<gNG, T>>>(p_h, gn2w, gn2b, p_a128, n);
    k_gemm<COUT, 0><<<gMM, 256>>>(p_a128, Wa, nullptr, p_ha, n);
    k_al<<<gNH_, T>>>(asrc, adst, n);
    k_attn<<<gNW, T>>>(aedg, ba, out, n);
}

// round 4
// speedup vs baseline: 2.3841x; 1.0423x over previous
#include <cuda_runtime.h>
#include <math.h>

#define NMAX 50000
#define EMAX 800000
#define CIN 64
#define COUT 128
#define NH 4

// ---------------- scratch ----------------------------------------------------
__device__ float    g_deg[NMAX];
__device__ float    g_dinv[NMAX];
__device__ float    g_btt[COUT];
__device__ unsigned g_fill;
__device__ int      g_count[NMAX];
__device__ int      g_ptr[NMAX + 1];
__device__ int      g_cursor[NMAX];
__device__ int      g_part[256];
__device__ int      g_pscan[256];
__device__ int      g_csr_r[EMAX];
__device__ float    g_csr_w[EMAX];
__device__ float    g_csr_c[EMAX];
__device__ float    g_a64 [NMAX * CIN];
__device__ float    g_xw  [NMAX * COUT];
__device__ float    g_h   [NMAX * COUT];
__device__ float    g_a128[NMAX * COUT];
__device__ float    g_res [NMAX * COUT];
__device__ float    g_ha  [NMAX * COUT];
__device__ float    g_als [NMAX * NH];
__device__ float    g_ald [NMAX * NH];

// ---------------- helpers ----------------------------------------------------
__device__ __forceinline__ float lrelu(float v, float s) { return v > 0.f ? v : s * v; }
__device__ __forceinline__ unsigned encf(float f) {
    unsigned u = __float_as_uint(f);
    return (u & 0x80000000u) ? ~u : (u | 0x80000000u);
}
__device__ __forceinline__ float decf(unsigned u) {
    return (u & 0x80000000u) ? __uint_as_float(u & 0x7fffffffu) : __uint_as_float(~u);
}

// ---------------- setup ------------------------------------------------------
__global__ void k_init(const float* __restrict__ teb, const float* __restrict__ b1, int n) {
    int i = blockIdx.x * blockDim.x + threadIdx.x;
    if (i == 0) g_fill = 0u;
    if (i < COUT) g_btt[i] = teb[i] + b1[i];
    if (i < n) { g_deg[i] = 1.0f; g_count[i] = 0; }
}

__global__ void k_count(const int* __restrict__ col, const float* __restrict__ ew, int E) {
    int e = blockIdx.x * blockDim.x + threadIdx.x;
    float w = 0.f;
    if (e < E) {
        w = ew[e];
        int c = col[e];
        atomicAdd(&g_count[c], 1);
        atomicAdd(&g_deg[c], w);
    }
    #pragma unroll
    for (int off = 16; off; off >>= 1) w = fmaxf(w, __shfl_down_sync(0xffffffffu, w, off));
    __shared__ float sm[8];
    int lane = threadIdx.x & 31, wid = threadIdx.x >> 5;
    if (lane == 0) sm[wid] = w;
    __syncthreads();
    if (threadIdx.x == 0) {
        float m = sm[0];
        #pragma unroll
        for (int i = 1; i < 8; i++) m = fmaxf(m, sm[i]);
        atomicMax(&g_fill, encf(m));
    }
}

__global__ void kScan1(int n1) {
    __shared__ int sm[256];
    int tid = threadIdx.x;
    int i = blockIdx.x * 256 + tid;
    int x = (i < n1 - 1) ? g_count[i] : 0;
    sm[tid] = x;
    __syncthreads();
    #pragma unroll
    for (int off = 1; off < 256; off <<= 1) {
        int v = (tid >= off) ? sm[tid - off] : 0;
        __syncthreads();
        sm[tid] += v;
        __syncthreads();
    }
    if (i < n1) g_ptr[i] = sm[tid] - x;
    if (tid == 255) g_part[blockIdx.x] = sm[255];
}

__global__ void kScan2(int nb) {
    __shared__ int sm[256];
    int tid = threadIdx.x;
    int x = (tid < nb) ? g_part[tid] : 0;
    sm[tid] = x;
    __syncthreads();
    #pragma unroll
    for (int off = 1; off < 256; off <<= 1) {
        int v = (tid >= off) ? sm[tid - off] : 0;
        __syncthreads();
        sm[tid] += v;
        __syncthreads();
    }
    g_pscan[tid] = sm[tid] - x;
}

__global__ void kScan3(int n1) {
    int i = blockIdx.x * blockDim.x + threadIdx.x;
    if (i < n1) {
        int v = g_ptr[i] + g_pscan[i >> 8];
        g_ptr[i] = v;
        if (i < n1 - 1) g_cursor[i] = v;
    }
}

__global__ void k_dinv(int n) {
    int i = blockIdx.x * blockDim.x + threadIdx.x;
    if (i < n) g_dinv[i] = rsqrtf(g_deg[i]);
}

__global__ void k_place(const int* __restrict__ row, const int* __restrict__ col,
                        const float* __restrict__ ew, int E) {
    int e = blockIdx.x * blockDim.x + threadIdx.x;
    if (e >= E) return;
    int c = col[e];
    int r = row[e];
    float w = ew[e];
    int slot = atomicAdd(&g_cursor[c], 1);
    g_csr_r[slot] = r;
    g_csr_w[slot] = w;
    g_csr_c[slot] = g_dinv[r] * w * g_dinv[c];
}

__global__ void k_tt_partial(const float* __restrict__ t, const float* __restrict__ tew) {
    int j = threadIdx.x;
    int k0 = blockIdx.x * 16;
    float acc = 0.f;
    #pragma unroll
    for (int k = 0; k < 16; k++) acc += lrelu(t[k0 + k], 0.01f) * tew[(k0 + k) * COUT + j];
    atomicAdd(&g_btt[j], acc);
}

// ---------------- group norm + LeakyReLU(0.01) -------------------------------
template <int C, int GS>
__global__ void k_gn(const float* __restrict__ x, const float* __restrict__ w,
                     const float* __restrict__ b, float* __restrict__ out, int n) {
    int idx = blockIdx.x * blockDim.x + threadIdx.x;
    if (idx >= n * 8) return;
    int node = idx >> 3, g = idx & 7;
    const float* xp = x + (size_t)node * C + g * GS;
    float v[GS];
    #pragma unroll
    for (int i = 0; i < GS; i += 4) {
        float4 t4 = *(const float4*)(xp + i);
        v[i] = t4.x; v[i + 1] = t4.y; v[i + 2] = t4.z; v[i + 3] = t4.w;
    }
    float s = 0.f, ss = 0.f;
    #pragma unroll
    for (int i = 0; i < GS; i++) { s += v[i]; ss += v[i] * v[i]; }
    float mean = s * (1.f / GS);
    float var  = ss * (1.f / GS) - mean * mean;
    float inv  = rsqrtf(var + 1e-5f);
    float* op = out + (size_t)node * C + g * GS;
    #pragma unroll
    for (int i = 0; i < GS; i += 4) {
        float4 o;
        o.x = lrelu((v[i    ] - mean) * inv * w[g * GS + i    ] + b[g * GS + i    ], 0.01f);
        o.y = lrelu((v[i + 1] - mean) * inv * w[g * GS + i + 1] + b[g * GS + i + 1], 0.01f);
        o.z = lrelu((v[i + 2] - mean) * inv * w[g * GS + i + 2] + b[g * GS + i + 2], 0.01f);
        o.w = lrelu((v[i + 3] - mean) * inv * w[g * GS + i + 3] + b[g * GS + i + 3], 0.01f);
        *(float4*)(op + i) = o;
    }
}

// ---------------- persistent SGEMM: [n,K] @ [K,128], W cached in smem --------
// 256 threads, BM=128, BK=16, 8x8/thread, double-buffered A slabs.
template <int K, int BIAS>
__global__ __launch_bounds__(256, 2)
void k_gemm(const float* __restrict__ A, const float* __restrict__ W,
            const float* __restrict__ bias, float* __restrict__ out, int n) {
    extern __shared__ float smem[];
    float* Ws = smem;                 // K*128
    float* As = smem + K * 128;       // 2 * 16 * 128
    const int S = K / 16;
    int tid = threadIdx.x;
    for (int i = tid * 4; i < K * 128; i += 1024)
        *(float4*)(Ws + i) = *(const float4*)(W + i);
    int tx = tid & 15, ty = tid >> 4;
    int lr = tid >> 1;
    int lk = (tid & 1) * 8;
    int tiles = (n + 127) >> 7;

    for (int tile = blockIdx.x; tile < tiles; tile += gridDim.x) {
        int m0 = tile << 7;
        int row = m0 + lr;
        bool rok = row < n;
        const float* arow = A + (size_t)row * K;
        float4 a0 = make_float4(0.f, 0.f, 0.f, 0.f), a1 = a0;
        if (rok) { a0 = *(const float4*)(arow + lk); a1 = *(const float4*)(arow + lk + 4); }
        float acc[8][8];
        #pragma unroll
        for (int i = 0; i < 8; i++)
            #pragma unroll
            for (int j = 0; j < 8; j++) acc[i][j] = 0.f;
        __syncthreads();
        {
            float* d = As + lk * 128 + lr;
            d[0] = a0.x; d[128] = a0.y; d[256] = a0.z; d[384] = a0.w;
            d[512] = a1.x; d[640] = a1.y; d[768] = a1.z; d[896] = a1.w;
        }
        __syncthreads();
        for (int s = 0; s < S; s++) {
            if (s + 1 < S && rok) {
                a0 = *(const float4*)(arow + (s + 1) * 16 + lk);
                a1 = *(const float4*)(arow + (s + 1) * 16 + lk + 4);
            }
            const float* as = As + (s & 1) * 2048;
            const float* ws = Ws + s * 16 * 128;
            #pragma unroll
            for (int k = 0; k < 16; k++) {
                float4 aa0 = *(const float4*)(as + k * 128 + ty * 8);
                float4 aa1 = *(const float4*)(as + k * 128 + ty * 8 + 4);
                float4 bb0 = *(const float4*)(ws + k * 128 + tx * 4);
                float4 bb1 = *(const float4*)(ws + k * 128 + 64 + tx * 4);
                float am[8] = {aa0.x, aa0.y, aa0.z, aa0.w, aa1.x, aa1.y, aa1.z, aa1.w};
                float bn[8] = {bb0.x, bb0.y, bb0.z, bb0.w, bb1.x, bb1.y, bb1.z, bb1.w};
                #pragma unroll
                for (int mi = 0; mi < 8; mi++)
                    #pragma unroll
                    for (int ni = 0; ni < 8; ni++) acc[mi][ni] += am[mi] * bn[ni];
            }
            if (s + 1 < S) {
                __syncthreads();
                float* d = As + ((s + 1) & 1) * 2048 + lk * 128 + lr;
                d[0] = a0.x; d[128] = a0.y; d[256] = a0.z; d[384] = a0.w;
                d[512] = a1.x; d[640] = a1.y; d[768] = a1.z; d[896] = a1.w;
                __syncthreads();
            }
        }
        #pragma unroll
        for (int mi = 0; mi < 8; mi++) {
            int m = m0 + ty * 8 + mi;
            if (m < n) {
                #pragma unroll
                for (int half = 0; half < 2; half++) {
                    int colb = half * 64 + tx * 4;
                    float4 o;
                    o.x = acc[mi][half * 4 + 0]; o.y = acc[mi][half * 4 + 1];
                    o.z = acc[mi][half * 4 + 2]; o.w = acc[mi][half * 4 + 3];
                    if (BIAS) {
                        float4 bb = *(const float4*)(bias + colb);
                        o.x += bb.x; o.y += bb.y; o.z += bb.z; o.w += bb.w;
                    }
                    *(float4*)(out + (size_t)m * 128 + colb) = o;
                }
            }
        }
    }
}

// ---------------- GCN conv: warp-per-node CSR gather -------------------------
template <int BASEVEC>
__global__ void k_conv(const float* __restrict__ src, const float* __restrict__ basep,
                       float* __restrict__ dst, int n) {
    int gw = (blockIdx.x * blockDim.x + threadIdx.x) >> 5;
    int lane = threadIdx.x & 31;
    if (gw >= n) return;
    int c = gw;
    int beg = g_ptr[c], end = g_ptr[c + 1];
    float dc = g_dinv[c];
    float4 base = BASEVEC ? *(const float4*)(g_btt + lane * 4)
                          : *(const float4*)(basep + (size_t)c * 128 + lane * 4);
    float4 sc = *(const float4*)(src + (size_t)c * 128 + lane * 4);
    float d2 = dc * dc;
    float4 acc;
    acc.x = base.x + d2 * sc.x; acc.y = base.y + d2 * sc.y;
    acc.z = base.z + d2 * sc.z; acc.w = base.w + d2 * sc.w;
    for (int b0 = beg; b0 < end; b0 += 32) {
        int cnt = min(32, end - b0);
        int ridx = 0; float cw = 0.f;
        if (lane < cnt) { ridx = g_csr_r[b0 + lane]; cw = g_csr_c[b0 + lane]; }
        for (int j = 0; j < cnt; j++) {
            int r = __shfl_sync(0xffffffffu, ridx, j);
            float coef = __shfl_sync(0xffffffffu, cw, j);
            float4 v = *(const float4*)(src + (size_t)r * 128 + lane * 4);
            acc.x += coef * v.x; acc.y += coef * v.y;
            acc.z += coef * v.z; acc.w += coef * v.w;
        }
    }
    *(float4*)(dst + (size_t)c * 128 + lane * 4) = acc;
}

// ---------------- attention projections --------------------------------------
__global__ void k_al(const float* __restrict__ asrc, const float* __restrict__ adst, int n) {
    int idx = blockIdx.x * blockDim.x + threadIdx.x;
    if (idx >= n * NH) return;
    int node = idx >> 2, h = idx & 3;
    const float4* hp = (const float4*)(g_ha + (size_t)node * COUT + h * 32);
    const float4* sp = (const float4*)(asrc + h * 32);
    const float4* dp = (const float4*)(adst + h * 32);
    float ds = 0.f, dd = 0.f;
    #pragma unroll
    for (int i = 0; i < 8; i++) {
        float4 v = hp[i], a = sp[i], b = dp[i];
        ds += v.x * a.x + v.y * a.y + v.z * a.z + v.w * a.w;
        dd += v.x * b.x + v.y * b.y + v.z * b.z + v.w * b.w;
    }
    g_als[idx] = ds;
    g_ald[idx] = dd;
}

// ---------------- fused GAT: warp-per-node, online softmax, 2 edge passes ----
__global__ __launch_bounds__(256)
void k_attn(const float* __restrict__ aedge, const float* __restrict__ ba,
            float* __restrict__ out, int n) {
    __shared__ float s_l[8][256];
    int gw = (blockIdx.x * blockDim.x + threadIdx.x) >> 5;
    int lane = threadIdx.x & 31;
    int wl = threadIdx.x >> 5;
    if (gw >= n) return;
    int c = gw;
    int beg = g_ptr[c], end = g_ptr[c + 1];
    int deg = end - beg;
    float4 ae = *(const float4*)aedge;
    float4 ad = *(const float4*)(g_ald + c * 4);
    float4 asl4 = *(const float4*)(g_als + c * 4);
    float fill = decf(g_fill);
    float l0 = lrelu(asl4.x + ad.x + ae.x * fill, 0.2f);
    float l1 = lrelu(asl4.y + ad.y + ae.y * fill, 0.2f);
    float l2 = lrelu(asl4.z + ad.z + ae.z * fill, 0.2f);
    float l3 = lrelu(asl4.w + ad.w + ae.w * fill, 0.2f);
    // pass 1: logits + lane-local online (m, s)
    float m0 = -1e30f, m1 = -1e30f, m2 = -1e30f, m3 = -1e30f;
    float t0 = 0.f, t1 = 0.f, t2 = 0.f, t3 = 0.f;
    for (int i = beg + lane; i < end; i += 32) {
        int r = g_csr_r[i];
        float w = g_csr_w[i];
        float4 as = *(const float4*)(g_als + r * 4);
        float a0 = lrelu(as.x + ad.x + ae.x * w, 0.2f);
        float a1 = lrelu(as.y + ad.y + ae.y * w, 0.2f);
        float a2 = lrelu(as.z + ad.z + ae.z * w, 0.2f);
        float a3 = lrelu(as.w + ad.w + ae.w * w, 0.2f);
        int il = i - beg;
        if (il < 64) *(float4*)(&s_l[wl][il * 4]) = make_float4(a0, a1, a2, a3);
        float nm;
        nm = fmaxf(m0, a0); t0 = t0 * __expf(m0 - nm) + __expf(a0 - nm); m0 = nm;
        nm = fmaxf(m1, a1); t1 = t1 * __expf(m1 - nm) + __expf(a1 - nm); m1 = nm;
        nm = fmaxf(m2, a2); t2 = t2 * __expf(m2 - nm) + __expf(a2 - nm); m2 = nm;
        nm = fmaxf(m3, a3); t3 = t3 * __expf(m3 - nm) + __expf(a3 - nm); m3 = nm;
    }
    #pragma unroll
    for (int off = 16; off; off >>= 1) {
        float om, ot, nm;
        om = __shfl_xor_sync(0xffffffffu, m0, off); ot = __shfl_xor_sync(0xffffffffu, t0, off);
        nm = fmaxf(m0, om); t0 = t0 * __expf(m0 - nm) + ot * __expf(om - nm); m0 = nm;
        om = __shfl_xor_sync(0xffffffffu, m1, off); ot = __shfl_xor_sync(0xffffffffu, t1, off);
        nm = fmaxf(m1, om); t1 = t1 * __expf(m1 - nm) + ot * __expf(om - nm); m1 = nm;
        om = __shfl_xor_sync(0xffffffffu, m2, off); ot = __shfl_xor_sync(0xffffffffu, t2, off);
        nm = fmaxf(m2, om); t2 = t2 * __expf(m2 - nm) + ot * __expf(om - nm); m2 = nm;
        om = __shfl_xor_sync(0xffffffffu, m3, off); ot = __shfl_xor_sync(0xffffffffu, t3, off);
        nm = fmaxf(m3, om); t3 = t3 * __expf(m3 - nm) + ot * __expf(om - nm); m3 = nm;
    }
    // merge self term
    float nm;
    nm = fmaxf(m0, l0); t0 = t0 * __expf(m0 - nm) + __expf(l0 - nm); m0 = nm;
    nm = fmaxf(m1, l1); t1 = t1 * __expf(m1 - nm) + __expf(l1 - nm); m1 = nm;
    nm = fmaxf(m2, l2); t2 = t2 * __expf(m2 - nm) + __expf(l2 - nm); m2 = nm;
    nm = fmaxf(m3, l3); t3 = t3 * __expf(m3 - nm) + __expf(l3 - nm); m3 = nm;
    float rs0 = 1.f / (t0 + 1e-16f), rs1 = 1.f / (t1 + 1e-16f);
    float rs2 = 1.f / (t2 + 1e-16f), rs3 = 1.f / (t3 + 1e-16f);
    // convert cached logits -> e
    int lim = min(deg, 64);
    for (int il = lane; il < lim; il += 32) {
        float4 lv = *(float4*)(&s_l[wl][il * 4]);
        lv.x = __expf(lv.x - m0); lv.y = __expf(lv.y - m1);
        lv.z = __expf(lv.z - m2); lv.w = __expf(lv.w - m3);
        *(float4*)(&s_l[wl][il * 4]) = lv;
    }
    __syncwarp();
    // pass 2: aggregation
    int h = lane >> 3;
    float rs  = (h == 0) ? rs0 : (h == 1) ? rs1 : (h == 2) ? rs2 : rs3;
    float mh  = (h == 0) ? m0  : (h == 1) ? m1  : (h == 2) ? m2  : m3;
    float aeh = (h == 0) ? ae.x : (h == 1) ? ae.y : (h == 2) ? ae.z : ae.w;
    float adh = (h == 0) ? ad.x : (h == 1) ? ad.y : (h == 2) ? ad.z : ad.w;
    float lh  = (h == 0) ? l0  : (h == 1) ? l1  : (h == 2) ? l2  : l3;
    float4 acc = *(const float4*)(ba + lane * 4);
    {
        float a_self = __expf(lh - mh) * rs;
        float4 vc = *(const float4*)(g_ha + (size_t)c * 128 + lane * 4);
        acc.x += a_self * vc.x; acc.y += a_self * vc.y;
        acc.z += a_self * vc.z; acc.w += a_self * vc.w;
    }
    for (int b0 = beg; b0 < end; b0 += 32) {
        int cnt = min(32, end - b0);
        int ridx = 0; float wreg = 0.f;
        if (lane < cnt) { ridx = g_csr_r[b0 + lane]; wreg = g_csr_w[b0 + lane]; }
        for (int j = 0; j < cnt; j++) {
            int r = __shfl_sync(0xffffffffu, ridx, j);
            int il = b0 + j - beg;
            float e;
            if (il < 64) {
                e = s_l[wl][il * 4 + h];
            } else {
                float w = __shfl_sync(0xffffffffu, wreg, j);
                float asv = __ldg(g_als + r * 4 + h);
                e = __expf(lrelu(asv + adh + aeh * w, 0.2f) - mh);
            }
            float alpha = e * rs;
            float4 v = *(const float4*)(g_ha + (size_t)r * 128 + lane * 4);
            acc.x += alpha * v.x; acc.y += alpha * v.y;
            acc.z += alpha * v.z; acc.w += alpha * v.w;
        }
    }
    *(float4*)(out + (size_t)c * 128 + lane * 4) = acc;
}

// ---------------- launch -----------------------------------------------------
extern "C" void kernel_launch(void* const* d_in, const int* in_sizes, int n_in,
                              void* d_out, int out_size) {
    const float* x    = (const float*)d_in[0];
    const float* t    = (const float*)d_in[1];
    const int*   ei   = (const int*)  d_in[2];
    const float* ew   = (const float*)d_in[3];
    const float* gn0w = (const float*)d_in[4];
    const float* gn0b = (const float*)d_in[5];
    const float* W1   = (const float*)d_in[6];
    const float* b1   = (const float*)d_in[7];
    const float* gn1w = (const float*)d_in[8];
    const float* gn1b = (const float*)d_in[9];
    const float* W2   = (const float*)d_in[10];
    const float* b2   = (const float*)d_in[11];
    const float* Wres = (const float*)d_in[12];
    const float* tew  = (const float*)d_in[13];
    const float* teb  = (const float*)d_in[14];
    const float* gn2w = (const float*)d_in[15];
    const float* gn2b = (const float*)d_in[16];
    const float* Wa   = (const float*)d_in[17];
    const float* asrc = (const float*)d_in[18];
    const float* adst = (const float*)d_in[19];
    const float* aedg = (const float*)d_in[20];
    const float* ba   = (const float*)d_in[21];

    int n = in_sizes[0] / CIN;
    int E = in_sizes[3];
    const int* row  = ei;
    const int* colp = ei + E;
    float* out = (float*)d_out;

    static cudaStream_t s1 = nullptr, s2 = nullptr;
    static cudaEvent_t evInit = nullptr, evCSR = nullptr, evRes = nullptr;
    if (!s1) {
        cudaStreamCreateWithFlags(&s1, cudaStreamNonBlocking);
        cudaStreamCreateWithFlags(&s2, cudaStreamNonBlocking);
        cudaEventCreateWithFlags(&evInit, cudaEventDisableTiming);
        cudaEventCreateWithFlags(&evCSR,  cudaEventDisableTiming);
        cudaEventCreateWithFlags(&evRes,  cudaEventDisableTiming);
        cudaFuncSetAttribute(k_gemm<CIN, 0>,  cudaFuncAttributeMaxDynamicSharedMemorySize, 49152);
        cudaFuncSetAttribute(k_gemm<CIN, 1>,  cudaFuncAttributeMaxDynamicSharedMemorySize, 49152);
        cudaFuncSetAttribute(k_gemm<COUT, 0>, cudaFuncAttributeMaxDynamicSharedMemorySize, 81920);
    }

    float *p_a64, *p_xw, *p_h, *p_a128, *p_res, *p_ha;
    cudaGetSymbolAddress((void**)&p_a64,  g_a64);
    cudaGetSymbolAddress((void**)&p_xw,   g_xw);
    cudaGetSymbolAddress((void**)&p_h,    g_h);
    cudaGetSymbolAddress((void**)&p_a128, g_a128);
    cudaGetSymbolAddress((void**)&p_res,  g_res);
    cudaGetSymbolAddress((void**)&p_ha,   g_ha);

    const int T = 256;
    int n1   = n + 1;
    int gN   = (n + T - 1) / T;
    int gE   = (E + T - 1) / T;
    int gNG  = (n * 8 + T - 1) / T;
    int gNH_ = (n * NH + T - 1) / T;
    int gNW  = (n * 32 + T - 1) / T;
    int gSC  = (n1 + 255) / 256;
    const int GG = 296;   // 2 blocks x 148 SMs

    // ---- fork ----
    k_init<<<gN, T>>>(teb, b1, n);
    cudaEventRecord(evInit, 0);

    // s1: CSR build + norm coefficients
    cudaStreamWaitEvent(s1, evInit, 0);
    k_count<<<gE, T, 0, s1>>>(colp, ew, E);
    kScan1<<<gSC, 256, 0, s1>>>(n1);
    kScan2<<<1, 256, 0, s1>>>(gSC);
    kScan3<<<gSC, 256, 0, s1>>>(n1);
    k_dinv<<<gN, T, 0, s1>>>(n);
    k_place<<<gE, T, 0, s1>>>(row, colp, ew, E);
    cudaEventRecord(evCSR, s1);

    // s2: residual GEMM (x @ Wres + b2)
    cudaStreamWaitEvent(s2, evInit, 0);
    k_gemm<CIN, 1><<<GG, 256, 49152, s2>>>(x, Wres, b2, p_res, n);
    cudaEventRecord(evRes, s2);

    // main: time embed + layer 1
    k_tt_partial<<<32, 128>>>(t, tew);
    k_gn<CIN, 8><<<gNG, T>>>(x, gn0w, gn0b, p_a64, n);
    k_gemm<CIN, 0><<<GG, 256, 49152>>>(p_a64, W1, nullptr, p_xw, n);
    cudaStreamWaitEvent(0, evCSR, 0);
    k_conv<1><<<gNW, T>>>(p_xw, nullptr, p_h, n);

    // layer 2 + residual
    k_gn<COUT, 16><<<gNG, T>>>(p_h, gn1w, gn1b, p_a128, n);
    k_gemm<COUT, 0><<<GG, 256, 81920>>>(p_a128, W2, nullptr, p_xw, n);
    cudaStreamWaitEvent(0, evRes, 0);
    k_conv<0><<<gNW, T>>>(p_xw, p_res, p_h, n);

    // GAT
    k_gn<COUT, 16><<<gNG, T>>>(p_h, gn2w, gn2b, p_a128, n);
    k_gemm<COUT, 0><<<GG, 256, 81920>>>(p_a128, Wa, nullptr, p_ha, n);
    k_al<<<gNH_, T>>>(asrc, adst, n);
    k_attn<<<gNW, T>>>(aedg, ba, out, n);
}

// round 5
// speedup vs baseline: 2.7684x; 1.1612x over previous
#include <cuda_runtime.h>
#include <cuda_fp16.h>
#include <math.h>

#define NMAX 50000
#define EMAX 800000
#define CIN 64
#define COUT 128
#define NH 4

// ---------------- scratch ----------------------------------------------------
__device__ float    g_deg[NMAX];
__device__ float    g_dinv[NMAX];
__device__ float    g_btt[COUT];
__device__ unsigned g_fill;
__device__ int      g_count[NMAX];
__device__ int      g_ptr[NMAX + 1];
__device__ int      g_cursor[NMAX];
__device__ int      g_part[256];
__device__ int      g_pscan[256];
__device__ int      g_csr_r[EMAX];
__device__ float    g_csr_w[EMAX];
__device__ float    g_csr_c[EMAX];
__device__ float    g_a64 [NMAX * CIN];
__device__ __half   g_xwh [NMAX * COUT];   // fp16 gather source
__device__ float    g_a128[NMAX * COUT];
__device__ float    g_res [NMAX * COUT];
__device__ float    g_ha  [NMAX * COUT];
__device__ float    g_als [NMAX * NH];
__device__ float    g_ald [NMAX * NH];

// ---------------- helpers ----------------------------------------------------
__device__ __forceinline__ float lrelu(float v, float s) { return v > 0.f ? v : s * v; }
__device__ __forceinline__ unsigned encf(float f) {
    unsigned u = __float_as_uint(f);
    return (u & 0x80000000u) ? ~u : (u | 0x80000000u);
}
__device__ __forceinline__ float decf(unsigned u) {
    return (u & 0x80000000u) ? __uint_as_float(u & 0x7fffffffu) : __uint_as_float(~u);
}

// packed 2-wide fp32 FMA (sm_100+; only reachable via PTX)
union F2U { float2 f; unsigned long long u; };
__device__ __forceinline__ void ffma2(F2U& d, F2U a, F2U b) {
    asm("fma.rn.f32x2 %0, %1, %2, %0;" : "+l"(d.u) : "l"(a.u), "l"(b.u));
}

// ---------------- setup ------------------------------------------------------
__global__ void k_init(const float* __restrict__ teb, const float* __restrict__ b1, int n) {
    int i = blockIdx.x * blockDim.x + threadIdx.x;
    if (i == 0) g_fill = 0u;
    if (i < COUT) g_btt[i] = teb[i] + b1[i];
    if (i < n) { g_deg[i] = 1.0f; g_count[i] = 0; }
}

__global__ void k_count(const int* __restrict__ col, const float* __restrict__ ew, int E) {
    int e = blockIdx.x * blockDim.x + threadIdx.x;
    float w = 0.f;
    if (e < E) {
        w = ew[e];
        int c = col[e];
        atomicAdd(&g_count[c], 1);
        atomicAdd(&g_deg[c], w);
    }
    #pragma unroll
    for (int off = 16; off; off >>= 1) w = fmaxf(w, __shfl_down_sync(0xffffffffu, w, off));
    __shared__ float sm[8];
    int lane = threadIdx.x & 31, wid = threadIdx.x >> 5;
    if (lane == 0) sm[wid] = w;
    __syncthreads();
    if (threadIdx.x == 0) {
        float m = sm[0];
        #pragma unroll
        for (int i = 1; i < 8; i++) m = fmaxf(m, sm[i]);
        atomicMax(&g_fill, encf(m));
    }
}

__global__ void kScan1(int n1) {
    __shared__ int sm[256];
    int tid = threadIdx.x;
    int i = blockIdx.x * 256 + tid;
    int x = (i < n1 - 1) ? g_count[i] : 0;
    sm[tid] = x;
    __syncthreads();
    #pragma unroll
    for (int off = 1; off < 256; off <<= 1) {
        int v = (tid >= off) ? sm[tid - off] : 0;
        __syncthreads();
        sm[tid] += v;
        __syncthreads();
    }
    if (i < n1) g_ptr[i] = sm[tid] - x;
    if (tid == 255) g_part[blockIdx.x] = sm[255];
}

__global__ void kScan2(int nb) {
    __shared__ int sm[256];
    int tid = threadIdx.x;
    int x = (tid < nb) ? g_part[tid] : 0;
    sm[tid] = x;
    __syncthreads();
    #pragma unroll
    for (int off = 1; off < 256; off <<= 1) {
        int v = (tid >= off) ? sm[tid - off] : 0;
        __syncthreads();
        sm[tid] += v;
        __syncthreads();
    }
    g_pscan[tid] = sm[tid] - x;
}

__global__ void kScan3(int n1) {     // also computes dinv
    int i = blockIdx.x * blockDim.x + threadIdx.x;
    if (i < n1) {
        int v = g_ptr[i] + g_pscan[i >> 8];
        g_ptr[i] = v;
        if (i < n1 - 1) {
            g_cursor[i] = v;
            g_dinv[i] = rsqrtf(g_deg[i]);
        }
    }
}

__global__ void k_place(const int* __restrict__ row, const int* __restrict__ col,
                        const float* __restrict__ ew, int E) {
    int e = blockIdx.x * blockDim.x + threadIdx.x;
    if (e >= E) return;
    int c = col[e];
    int r = row[e];
    float w = ew[e];
    int slot = atomicAdd(&g_cursor[c], 1);
    g_csr_r[slot] = r;
    g_csr_w[slot] = w;
    g_csr_c[slot] = g_dinv[r] * w * g_dinv[c];
}

__global__ void k_tt_partial(const float* __restrict__ t, const float* __restrict__ tew) {
    int j = threadIdx.x;
    int k0 = blockIdx.x * 16;
    float acc = 0.f;
    #pragma unroll
    for (int k = 0; k < 16; k++) acc += lrelu(t[k0 + k], 0.01f) * tew[(k0 + k) * COUT + j];
    atomicAdd(&g_btt[j], acc);
}

// ---------------- group norm + LeakyReLU(0.01) for x (64 ch) -----------------
__global__ void k_gn0(const float* __restrict__ x, const float* __restrict__ w,
                      const float* __restrict__ b, float* __restrict__ out, int n) {
    int idx = blockIdx.x * blockDim.x + threadIdx.x;
    if (idx >= n * 8) return;
    int node = idx >> 3, g = idx & 7;
    const float* xp = x + (size_t)node * CIN + g * 8;
    float v[8];
    #pragma unroll
    for (int i = 0; i < 8; i += 4) {
        float4 t4 = *(const float4*)(xp + i);
        v[i] = t4.x; v[i + 1] = t4.y; v[i + 2] = t4.z; v[i + 3] = t4.w;
    }
    float s = 0.f, ss = 0.f;
    #pragma unroll
    for (int i = 0; i < 8; i++) { s += v[i]; ss += v[i] * v[i]; }
    float mean = s * 0.125f;
    float var  = ss * 0.125f - mean * mean;
    float inv  = rsqrtf(var + 1e-5f);
    float* op = out + (size_t)node * CIN + g * 8;
    #pragma unroll
    for (int i = 0; i < 8; i += 4) {
        float4 o;
        o.x = lrelu((v[i    ] - mean) * inv * w[g * 8 + i    ] + b[g * 8 + i    ], 0.01f);
        o.y = lrelu((v[i + 1] - mean) * inv * w[g * 8 + i + 1] + b[g * 8 + i + 1], 0.01f);
        o.z = lrelu((v[i + 2] - mean) * inv * w[g * 8 + i + 2] + b[g * 8 + i + 2], 0.01f);
        o.w = lrelu((v[i + 3] - mean) * inv * w[g * 8 + i + 3] + b[g * 8 + i + 3], 0.01f);
        *(float4*)(op + i) = o;
    }
}

// ---------------- persistent FFMA2 SGEMM: [n,K] @ [K,128] --------------------
// W cached in smem, A double-buffered, 8x8/thread via packed f32x2 FMA.
// OUTH=1: write fp16 to outh; else fp32 to out (BIAS adds bias[j]).
template <int K, int BIAS, int OUTH>
__global__ __launch_bounds__(256, 2)
void k_gemm(const float* __restrict__ A, const float* __restrict__ W,
            const float* __restrict__ bias, float* __restrict__ out,
            __half* __restrict__ outh, int n) {
    extern __shared__ float smem[];
    float* Ws = smem;                 // K*128
    float* As = smem + K * 128;       // 2 * 16 * 128
    const int S = K / 16;
    int tid = threadIdx.x;
    for (int i = tid * 4; i < K * 128; i += 1024)
        *(float4*)(Ws + i) = *(const float4*)(W + i);
    int tx = tid & 15, ty = tid >> 4;
    int lr = tid >> 1;
    int lk = (tid & 1) * 8;
    int tiles = (n + 127) >> 7;

    for (int tile = blockIdx.x; tile < tiles; tile += gridDim.x) {
        int m0 = tile << 7;
        int row = m0 + lr;
        bool rok = row < n;
        const float* arow = A + (size_t)row * K;
        float4 a0 = make_float4(0.f, 0.f, 0.f, 0.f), a1 = a0;
        if (rok) { a0 = *(const float4*)(arow + lk); a1 = *(const float4*)(arow + lk + 4); }
        F2U acc2[8][4];
        #pragma unroll
        for (int i = 0; i < 8; i++)
            #pragma unroll
            for (int j = 0; j < 4; j++) acc2[i][j].f = make_float2(0.f, 0.f);
        __syncthreads();
        {
            float* d = As + lk * 128 + lr;
            d[0] = a0.x; d[128] = a0.y; d[256] = a0.z; d[384] = a0.w;
            d[512] = a1.x; d[640] = a1.y; d[768] = a1.z; d[896] = a1.w;
        }
        __syncthreads();
        for (int s = 0; s < S; s++) {
            if (s + 1 < S && rok) {
                a0 = *(const float4*)(arow + (s + 1) * 16 + lk);
                a1 = *(const float4*)(arow + (s + 1) * 16 + lk + 4);
            }
            const float* as = As + (s & 1) * 2048;
            const float* ws = Ws + s * 16 * 128;
            #pragma unroll
            for (int k = 0; k < 16; k++) {
                float4 aa0 = *(const float4*)(as + k * 128 + ty * 8);
                float4 aa1 = *(const float4*)(as + k * 128 + ty * 8 + 4);
                float4 bb0 = *(const float4*)(ws + k * 128 + tx * 4);
                float4 bb1 = *(const float4*)(ws + k * 128 + 64 + tx * 4);
                F2U bp[4];
                bp[0].f = make_float2(bb0.x, bb0.y); bp[1].f = make_float2(bb0.z, bb0.w);
                bp[2].f = make_float2(bb1.x, bb1.y); bp[3].f = make_float2(bb1.z, bb1.w);
                float am[8] = {aa0.x, aa0.y, aa0.z, aa0.w, aa1.x, aa1.y, aa1.z, aa1.w};
                #pragma unroll
                for (int mi = 0; mi < 8; mi++) {
                    F2U ap; ap.f = make_float2(am[mi], am[mi]);
                    #pragma unroll
                    for (int nj = 0; nj < 4; nj++) ffma2(acc2[mi][nj], ap, bp[nj]);
                }
            }
            if (s + 1 < S) {
                __syncthreads();
                float* d = As + ((s + 1) & 1) * 2048 + lk * 128 + lr;
                d[0] = a0.x; d[128] = a0.y; d[256] = a0.z; d[384] = a0.w;
                d[512] = a1.x; d[640] = a1.y; d[768] = a1.z; d[896] = a1.w;
                __syncthreads();
            }
        }
        #pragma unroll
        for (int mi = 0; mi < 8; mi++) {
            int m = m0 + ty * 8 + mi;
            if (m < n) {
                #pragma unroll
                for (int half = 0; half < 2; half++) {
                    int colb = half * 64 + tx * 4;
                    float4 o;
                    o.x = acc2[mi][half * 2 + 0].f.x; o.y = acc2[mi][half * 2 + 0].f.y;
                    o.z = acc2[mi][half * 2 + 1].f.x; o.w = acc2[mi][half * 2 + 1].f.y;
                    if (BIAS) {
                        float4 bb = *(const float4*)(bias + colb);
                        o.x += bb.x; o.y += bb.y; o.z += bb.z; o.w += bb.w;
                    }
                    if (OUTH) {
                        __half2* hp = (__half2*)(outh + (size_t)m * 128 + colb);
                        hp[0] = __floats2half2_rn(o.x, o.y);
                        hp[1] = __floats2half2_rn(o.z, o.w);
                    } else {
                        *(float4*)(out + (size_t)m * 128 + colb) = o;
                    }
                }
            }
        }
    }
}

// ---------------- GCN conv (fp16 gather) + fused GN + LeakyReLU --------------
// acc = base + dinv[c]^2*src[c] + sum_e coef*src[r]; out = lrelu(GN(acc))
template <int BASEVEC>
__global__ void k_conv(const __half* __restrict__ srch, const float* __restrict__ basep,
                       float* __restrict__ dst, const float* __restrict__ gnw,
                       const float* __restrict__ gnb, int n) {
    int gw = (blockIdx.x * blockDim.x + threadIdx.x) >> 5;
    int lane = threadIdx.x & 31;
    if (gw >= n) return;
    int c = gw;
    int beg = g_ptr[c], end = g_ptr[c + 1];
    float dc = g_dinv[c];
    float4 base = BASEVEC ? *(const float4*)(g_btt + lane * 4)
                          : *(const float4*)(basep + (size_t)c * 128 + lane * 4);
    float d2 = dc * dc;
    float4 acc;
    {
        const __half2* sp = (const __half2*)(srch + (size_t)c * 128 + lane * 4);
        float2 lo = __half22float2(sp[0]), hi = __half22float2(sp[1]);
        acc.x = base.x + d2 * lo.x; acc.y = base.y + d2 * lo.y;
        acc.z = base.z + d2 * hi.x; acc.w = base.w + d2 * hi.y;
    }
    for (int b0 = beg; b0 < end; b0 += 32) {
        int cnt = min(32, end - b0);
        int ridx = 0; float cw = 0.f;
        if (lane < cnt) { ridx = g_csr_r[b0 + lane]; cw = g_csr_c[b0 + lane]; }
        for (int j = 0; j < cnt; j++) {
            int r = __shfl_sync(0xffffffffu, ridx, j);
            float coef = __shfl_sync(0xffffffffu, cw, j);
            const __half2* sp = (const __half2*)(srch + (size_t)r * 128 + lane * 4);
            float2 lo = __half22float2(sp[0]), hi = __half22float2(sp[1]);
            acc.x += coef * lo.x; acc.y += coef * lo.y;
            acc.z += coef * hi.x; acc.w += coef * hi.y;
        }
    }
    // fused GroupNorm(8 groups of 16ch = 4 lanes) + LeakyReLU(0.01)
    float s  = acc.x + acc.y + acc.z + acc.w;
    float ss = acc.x * acc.x + acc.y * acc.y + acc.z * acc.z + acc.w * acc.w;
    s  += __shfl_xor_sync(0xffffffffu, s, 1);  ss += __shfl_xor_sync(0xffffffffu, ss, 1);
    s  += __shfl_xor_sync(0xffffffffu, s, 2);  ss += __shfl_xor_sync(0xffffffffu, ss, 2);
    float mean = s * (1.f / 16.f);
    float var  = ss * (1.f / 16.f) - mean * mean;
    float inv  = rsqrtf(var + 1e-5f);
    float4 wv = *(const float4*)(gnw + lane * 4);
    float4 bv = *(const float4*)(gnb + lane * 4);
    float4 o;
    o.x = lrelu((acc.x - mean) * inv * wv.x + bv.x, 0.01f);
    o.y = lrelu((acc.y - mean) * inv * wv.y + bv.y, 0.01f);
    o.z = lrelu((acc.z - mean) * inv * wv.z + bv.z, 0.01f);
    o.w = lrelu((acc.w - mean) * inv * wv.w + bv.w, 0.01f);
    *(float4*)(dst + (size_t)c * 128 + lane * 4) = o;
}

// ---------------- attention projections --------------------------------------
__global__ void k_al(const float* __restrict__ asrc, const float* __restrict__ adst, int n) {
    int idx = blockIdx.x * blockDim.x + threadIdx.x;
    if (idx >= n * NH) return;
    int node = idx >> 2, h = idx & 3;
    const float4* hp = (const float4*)(g_ha + (size_t)node * COUT + h * 32);
    const float4* sp = (const float4*)(asrc + h * 32);
    const float4* dp = (const float4*)(adst + h * 32);
    float ds = 0.f, dd = 0.f;
    #pragma unroll
    for (int i = 0; i < 8; i++) {
        float4 v = hp[i], a = sp[i], b = dp[i];
        ds += v.x * a.x + v.y * a.y + v.z * a.z + v.w * a.w;
        dd += v.x * b.x + v.y * b.y + v.z * b.z + v.w * b.w;
    }
    g_als[idx] = ds;
    g_ald[idx] = dd;
}

// ---------------- fused GAT: warp-per-node, online softmax -------------------
__global__ __launch_bounds__(256)
void k_attn(const float* __restrict__ aedge, const float* __restrict__ ba,
            float* __restrict__ out, int n) {
    __shared__ float s_l[8][256];
    int gw = (blockIdx.x * blockDim.x + threadIdx.x) >> 5;
    int lane = threadIdx.x & 31;
    int wl = threadIdx.x >> 5;
    if (gw >= n) return;
    int c = gw;
    int beg = g_ptr[c], end = g_ptr[c + 1];
    int deg = end - beg;
    float4 ae = *(const float4*)aedge;
    float4 ad = *(const float4*)(g_ald + c * 4);
    float4 asl4 = *(const float4*)(g_als + c * 4);
    float fill = decf(g_fill);
    float l0 = lrelu(asl4.x + ad.x + ae.x * fill, 0.2f);
    float l1 = lrelu(asl4.y + ad.y + ae.y * fill, 0.2f);
    float l2 = lrelu(asl4.z + ad.z + ae.z * fill, 0.2f);
    float l3 = lrelu(asl4.w + ad.w + ae.w * fill, 0.2f);
    float m0 = -1e30f, m1 = -1e30f, m2 = -1e30f, m3 = -1e30f;
    float t0 = 0.f, t1 = 0.f, t2 = 0.f, t3 = 0.f;
    for (int i = beg + lane; i < end; i += 32) {
        int r = g_csr_r[i];
        float w = g_csr_w[i];
        float4 as = *(const float4*)(g_als + r * 4);
        float a0 = lrelu(as.x + ad.x + ae.x * w, 0.2f);
        float a1 = lrelu(as.y + ad.y + ae.y * w, 0.2f);
        float a2 = lrelu(as.z + ad.z + ae.z * w, 0.2f);
        float a3 = lrelu(as.w + ad.w + ae.w * w, 0.2f);
        int il = i - beg;
        if (il < 64) *(float4*)(&s_l[wl][il * 4]) = make_float4(a0, a1, a2, a3);
        float nm;
        nm = fmaxf(m0, a0); t0 = t0 * __expf(m0 - nm) + __expf(a0 - nm); m0 = nm;
        nm = fmaxf(m1, a1); t1 = t1 * __expf(m1 - nm) + __expf(a1 - nm); m1 = nm;
        nm = fmaxf(m2, a2); t2 = t2 * __expf(m2 - nm) + __expf(a2 - nm); m2 = nm;
        nm = fmaxf(m3, a3); t3 = t3 * __expf(m3 - nm) + __expf(a3 - nm); m3 = nm;
    }
    #pragma unroll
    for (int off = 16; off; off >>= 1) {
        float om, ot, nm;
        om = __shfl_xor_sync(0xffffffffu, m0, off); ot = __shfl_xor_sync(0xffffffffu, t0, off);
        nm = fmaxf(m0, om); t0 = t0 * __expf(m0 - nm) + ot * __expf(om - nm); m0 = nm;
        om = __shfl_xor_sync(0xffffffffu, m1, off); ot = __shfl_xor_sync(0xffffffffu, t1, off);
        nm = fmaxf(m1, om); t1 = t1 * __expf(m1 - nm) + ot * __expf(om - nm); m1 = nm;
        om = __shfl_xor_sync(0xffffffffu, m2, off); ot = __shfl_xor_sync(0xffffffffu, t2, off);
        nm = fmaxf(m2, om); t2 = t2 * __expf(m2 - nm) + ot * __expf(om - nm); m2 = nm;
        om = __shfl_xor_sync(0xffffffffu, m3, off); ot = __shfl_xor_sync(0xffffffffu, t3, off);
        nm = fmaxf(m3, om); t3 = t3 * __expf(m3 - nm) + ot * __expf(om - nm); m3 = nm;
    }
    float nm;
    nm = fmaxf(m0, l0); t0 = t0 * __expf(m0 - nm) + __expf(l0 - nm); m0 = nm;
    nm = fmaxf(m1, l1); t1 = t1 * __expf(m1 - nm) + __expf(l1 - nm); m1 = nm;
    nm = fmaxf(m2, l2); t2 = t2 * __expf(m2 - nm) + __expf(l2 - nm); m2 = nm;
    nm = fmaxf(m3, l3); t3 = t3 * __expf(m3 - nm) + __expf(l3 - nm); m3 = nm;
    float rs0 = 1.f / (t0 + 1e-16f), rs1 = 1.f / (t1 + 1e-16f);
    float rs2 = 1.f / (t2 + 1e-16f), rs3 = 1.f / (t3 + 1e-16f);
    int lim = min(deg, 64);
    for (int il = lane; il < lim; il += 32) {
        float4 lv = *(float4*)(&s_l[wl][il * 4]);
        lv.x = __expf(lv.x - m0); lv.y = __expf(lv.y - m1);
        lv.z = __expf(lv.z - m2); lv.w = __expf(lv.w - m3);
        *(float4*)(&s_l[wl][il * 4]) = lv;
    }
    __syncwarp();
    int h = lane >> 3;
    float rs  = (h == 0) ? rs0 : (h == 1) ? rs1 : (h == 2) ? rs2 : rs3;
    float mh  = (h == 0) ? m0  : (h == 1) ? m1  : (h == 2) ? m2  : m3;
    float aeh = (h == 0) ? ae.x : (h == 1) ? ae.y : (h == 2) ? ae.z : ae.w;
    float adh = (h == 0) ? ad.x : (h == 1) ? ad.y : (h == 2) ? ad.z : ad.w;
    float lh  = (h == 0) ? l0  : (h == 1) ? l1  : (h == 2) ? l2  : l3;
    float4 acc = *(const float4*)(ba + lane * 4);
    {
        float a_self = __expf(lh - mh) * rs;
        float4 vc = *(const float4*)(g_ha + (size_t)c * 128 + lane * 4);
        acc.x += a_self * vc.x; acc.y += a_self * vc.y;
        acc.z += a_self * vc.z; acc.w += a_self * vc.w;
    }
    for (int b0 = beg; b0 < end; b0 += 32) {
        int cnt = min(32, end - b0);
        int ridx = 0; float wreg = 0.f;
        if (lane < cnt) { ridx = g_csr_r[b0 + lane]; wreg = g_csr_w[b0 + lane]; }
        for (int j = 0; j < cnt; j++) {
            int r = __shfl_sync(0xffffffffu, ridx, j);
            int il = b0 + j - beg;
            float e;
            if (il < 64) {
                e = s_l[wl][il * 4 + h];
            } else {
                float w = __shfl_sync(0xffffffffu, wreg, j);
                float asv = __ldg(g_als + r * 4 + h);
                e = __expf(lrelu(asv + adh + aeh * w, 0.2f) - mh);
            }
            float alpha = e * rs;
            float4 v = *(const float4*)(g_ha + (size_t)r * 128 + lane * 4);
            acc.x += alpha * v.x; acc.y += alpha * v.y;
            acc.z += alpha * v.z; acc.w += alpha * v.w;
        }
    }
    *(float4*)(out + (size_t)c * 128 + lane * 4) = acc;
}

// ---------------- launch -----------------------------------------------------
extern "C" void kernel_launch(void* const* d_in, const int* in_sizes, int n_in,
                              void* d_out, int out_size) {
    const float* x    = (const float*)d_in[0];
    const float* t    = (const float*)d_in[1];
    const int*   ei   = (const int*)  d_in[2];
    const float* ew   = (const float*)d_in[3];
    const float* gn0w = (const float*)d_in[4];
    const float* gn0b = (const float*)d_in[5];
    const float* W1   = (const float*)d_in[6];
    const float* b1   = (const float*)d_in[7];
    const float* gn1w = (const float*)d_in[8];
    const float* gn1b = (const float*)d_in[9];
    const float* W2   = (const float*)d_in[10];
    const float* b2   = (const float*)d_in[11];
    const float* Wres = (const float*)d_in[12];
    const float* tew  = (const float*)d_in[13];
    const float* teb  = (const float*)d_in[14];
    const float* gn2w = (const float*)d_in[15];
    const float* gn2b = (const float*)d_in[16];
    const float* Wa   = (const float*)d_in[17];
    const float* asrc = (const float*)d_in[18];
    const float* adst = (const float*)d_in[19];
    const float* aedg = (const float*)d_in[20];
    const float* ba   = (const float*)d_in[21];

    int n = in_sizes[0] / CIN;
    int E = in_sizes[3];
    const int* row  = ei;
    const int* colp = ei + E;
    float* out = (float*)d_out;

    static cudaStream_t s1 = nullptr, s2 = nullptr;
    static cudaEvent_t evInit = nullptr, evCSR = nullptr, evRes = nullptr;
    if (!s1) {
        cudaStreamCreateWithFlags(&s1, cudaStreamNonBlocking);
        cudaStreamCreateWithFlags(&s2, cudaStreamNonBlocking);
        cudaEventCreateWithFlags(&evInit, cudaEventDisableTiming);
        cudaEventCreateWithFlags(&evCSR,  cudaEventDisableTiming);
        cudaEventCreateWithFlags(&evRes,  cudaEventDisableTiming);
        cudaFuncSetAttribute(k_gemm<CIN, 0, 1>,  cudaFuncAttributeMaxDynamicSharedMemorySize, 49152);
        cudaFuncSetAttribute(k_gemm<CIN, 1, 0>,  cudaFuncAttributeMaxDynamicSharedMemorySize, 49152);
        cudaFuncSetAttribute(k_gemm<COUT, 0, 1>, cudaFuncAttributeMaxDynamicSharedMemorySize, 81920);
        cudaFuncSetAttribute(k_gemm<COUT, 0, 0>, cudaFuncAttributeMaxDynamicSharedMemorySize, 81920);
    }

    float *p_a64, *p_a128, *p_res, *p_ha;
    __half* p_xwh;
    cudaGetSymbolAddress((void**)&p_a64,  g_a64);
    cudaGetSymbolAddress((void**)&p_xwh,  g_xwh);
    cudaGetSymbolAddress((void**)&p_a128, g_a128);
    cudaGetSymbolAddress((void**)&p_res,  g_res);
    cudaGetSymbolAddress((void**)&p_ha,   g_ha);

    const int T = 256;
    int n1   = n + 1;
    int gN   = (n + T - 1) / T;
    int gE   = (E + T - 1) / T;
    int gNG  = (n * 8 + T - 1) / T;
    int gNH_ = (n * NH + T - 1) / T;
    int gNW  = (n * 32 + T - 1) / T;
    int gSC  = (n1 + 255) / 256;
    const int GG = 296;

    // launch index 0
    k_init<<<gN, T>>>(teb, b1, n);
    cudaEventRecord(evInit, 0);

    // s1: CSR build (indices 1-4, then 6)
    cudaStreamWaitEvent(s1, evInit, 0);
    k_count<<<gE, T, 0, s1>>>(colp, ew, E);
    kScan1<<<gSC, 256, 0, s1>>>(n1);
    kScan2<<<1, 256, 0, s1>>>(gSC);
    kScan3<<<gSC, 256, 0, s1>>>(n1);

    // s2: residual FFMA2 GEMM — launch index 5 (captured by ncu -s 5 -c 1)
    cudaStreamWaitEvent(s2, evInit, 0);
    k_gemm<CIN, 1, 0><<<GG, 256, 49152, s2>>>(x, Wres, b2, p_res, nullptr, n);
    cudaEventRecord(evRes, s2);

    k_place<<<gE, T, 0, s1>>>(row, colp, ew, E);
    cudaEventRecord(evCSR, s1);

    // main chain
    k_tt_partial<<<32, 128>>>(t, tew);
    k_gn0<<<gNG, T>>>(x, gn0w, gn0b, p_a64, n);
    k_gemm<CIN, 0, 1><<<GG, 256, 49152>>>(p_a64, W1, nullptr, nullptr, p_xwh, n);
    cudaStreamWaitEvent(0, evCSR, 0);
    k_conv<1><<<gNW, T>>>(p_xwh, nullptr, p_a128, gn1w, gn1b, n);      // -> gn1(lrelu) out

    k_gemm<COUT, 0, 1><<<GG, 256, 81920>>>(p_a128, W2, nullptr, nullptr, p_xwh, n);
    cudaStreamWaitEvent(0, evRes, 0);
    k_conv<0><<<gNW, T>>>(p_xwh, p_res, p_a128, gn2w, gn2b, n);        // -> gn2(lrelu) out

    k_gemm<COUT, 0, 0><<<GG, 256, 81920>>>(p_a128, Wa, nullptr, p_ha, nullptr, n);
    k_al<<<gNH_, T>>>(asrc, adst, n);
    k_attn<<<gNW, T>>>(aedg, ba, out, n);
}

// round 6
// speedup vs baseline: 3.0924x; 1.1170x over previous
#include <cuda_runtime.h>
#include <cuda_fp16.h>
#include <math.h>

#define NMAX 50000
#define EMAX 800000
#define CIN 64
#define COUT 128
#define NH 4

// ---------------- scratch ----------------------------------------------------
__device__ float    g_deg[NMAX];
__device__ float    g_dinv[NMAX];
__device__ float    g_btt[COUT];
__device__ unsigned g_fill;
__device__ int      g_count[NMAX];
__device__ int      g_ptr[NMAX + 1];
__device__ int      g_cursor[NMAX];
__device__ int      g_part[256];
__device__ int      g_pscan[256];
__device__ int      g_csr_r[EMAX];
__device__ float    g_csr_w[EMAX];
__device__ float    g_csr_c[EMAX];
__device__ float    g_a64 [NMAX * CIN];
__device__ __half   g_xwh [NMAX * COUT];   // fp16 gather source (GCN)
__device__ __half   g_hah [NMAX * COUT];   // fp16 attention features
__device__ float    g_a128[NMAX * COUT];
__device__ float    g_res [NMAX * COUT];
__device__ float    g_als [NMAX * NH];
__device__ float    g_ald [NMAX * NH];

// ---------------- helpers ----------------------------------------------------
__device__ __forceinline__ float lrelu(float v, float s) { return v > 0.f ? v : s * v; }
__device__ __forceinline__ unsigned encf(float f) {
    unsigned u = __float_as_uint(f);
    return (u & 0x80000000u) ? ~u : (u | 0x80000000u);
}
__device__ __forceinline__ float decf(unsigned u) {
    return (u & 0x80000000u) ? __uint_as_float(u & 0x7fffffffu) : __uint_as_float(~u);
}
__device__ __forceinline__ unsigned f2tf32(float f) {
    unsigned u; asm("cvt.rna.tf32.f32 %0, %1;" : "=r"(u) : "f"(f)); return u;
}
__device__ __forceinline__ void mma_tf32(float* c, const unsigned* a, const unsigned* b) {
    asm("mma.sync.aligned.m16n8k8.row.col.f32.tf32.tf32.f32 "
        "{%0,%1,%2,%3}, {%4,%5,%6,%7}, {%8,%9}, {%0,%1,%2,%3};"
        : "+f"(c[0]), "+f"(c[1]), "+f"(c[2]), "+f"(c[3])
        : "r"(a[0]), "r"(a[1]), "r"(a[2]), "r"(a[3]), "r"(b[0]), "r"(b[1]));
}

// ---------------- setup ------------------------------------------------------
__global__ void k_init(const float* __restrict__ teb, const float* __restrict__ b1, int n) {
    int i = blockIdx.x * blockDim.x + threadIdx.x;
    if (i == 0) g_fill = 0u;
    if (i < COUT) g_btt[i] = teb[i] + b1[i];
    if (i < n) { g_deg[i] = 1.0f; g_count[i] = 0; }
}

__global__ void k_count(const int* __restrict__ col, const float* __restrict__ ew, int E) {
    int e = blockIdx.x * blockDim.x + threadIdx.x;
    float w = 0.f;
    if (e < E) {
        w = ew[e];
        int c = col[e];
        atomicAdd(&g_count[c], 1);
        atomicAdd(&g_deg[c], w);
    }
    #pragma unroll
    for (int off = 16; off; off >>= 1) w = fmaxf(w, __shfl_down_sync(0xffffffffu, w, off));
    __shared__ float sm[8];
    int lane = threadIdx.x & 31, wid = threadIdx.x >> 5;
    if (lane == 0) sm[wid] = w;
    __syncthreads();
    if (threadIdx.x == 0) {
        float m = sm[0];
        #pragma unroll
        for (int i = 1; i < 8; i++) m = fmaxf(m, sm[i]);
        atomicMax(&g_fill, encf(m));
    }
}

__global__ void kScan1(int n1) {
    __shared__ int sm[256];
    int tid = threadIdx.x;
    int i = blockIdx.x * 256 + tid;
    int x = (i < n1 - 1) ? g_count[i] : 0;
    sm[tid] = x;
    __syncthreads();
    #pragma unroll
    for (int off = 1; off < 256; off <<= 1) {
        int v = (tid >= off) ? sm[tid - off] : 0;
        __syncthreads();
        sm[tid] += v;
        __syncthreads();
    }
    if (i < n1) g_ptr[i] = sm[tid] - x;
    if (tid == 255) g_part[blockIdx.x] = sm[255];
}

__global__ void kScan2(int nb) {
    __shared__ int sm[256];
    int tid = threadIdx.x;
    int x = (tid < nb) ? g_part[tid] : 0;
    sm[tid] = x;
    __syncthreads();
    #pragma unroll
    for (int off = 1; off < 256; off <<= 1) {
        int v = (tid >= off) ? sm[tid - off] : 0;
        __syncthreads();
        sm[tid] += v;
        __syncthreads();
    }
    g_pscan[tid] = sm[tid] - x;
}

__global__ void kScan3(int n1) {
    int i = blockIdx.x * blockDim.x + threadIdx.x;
    if (i < n1) {
        int v = g_ptr[i] + g_pscan[i >> 8];
        g_ptr[i] = v;
        if (i < n1 - 1) {
            g_cursor[i] = v;
            g_dinv[i] = rsqrtf(g_deg[i]);
        }
    }
}

__global__ void k_place(const int* __restrict__ row, const int* __restrict__ col,
                        const float* __restrict__ ew, int E) {
    int e = blockIdx.x * blockDim.x + threadIdx.x;
    if (e >= E) return;
    int c = col[e];
    int r = row[e];
    float w = ew[e];
    int slot = atomicAdd(&g_cursor[c], 1);
    g_csr_r[slot] = r;
    g_csr_w[slot] = w;
    g_csr_c[slot] = g_dinv[r] * w * g_dinv[c];
}

__global__ void k_tt_partial(const float* __restrict__ t, const float* __restrict__ tew) {
    int j = threadIdx.x;
    int k0 = blockIdx.x * 16;
    float acc = 0.f;
    #pragma unroll
    for (int k = 0; k < 16; k++) acc += lrelu(t[k0 + k], 0.01f) * tew[(k0 + k) * COUT + j];
    atomicAdd(&g_btt[j], acc);
}

// ---------------- group norm + LeakyReLU(0.01) for x (64 ch) -----------------
__global__ void k_gn0(const float* __restrict__ x, const float* __restrict__ w,
                      const float* __restrict__ b, float* __restrict__ out, int n) {
    int idx = blockIdx.x * blockDim.x + threadIdx.x;
    if (idx >= n * 8) return;
    int node = idx >> 3, g = idx & 7;
    const float* xp = x + (size_t)node * CIN + g * 8;
    float v[8];
    #pragma unroll
    for (int i = 0; i < 8; i += 4) {
        float4 t4 = *(const float4*)(xp + i);
        v[i] = t4.x; v[i + 1] = t4.y; v[i + 2] = t4.z; v[i + 3] = t4.w;
    }
    float s = 0.f, ss = 0.f;
    #pragma unroll
    for (int i = 0; i < 8; i++) { s += v[i]; ss += v[i] * v[i]; }
    float mean = s * 0.125f;
    float var  = ss * 0.125f - mean * mean;
    float inv  = rsqrtf(var + 1e-5f);
    float* op = out + (size_t)node * CIN + g * 8;
    #pragma unroll
    for (int i = 0; i < 8; i += 4) {
        float4 o;
        o.x = lrelu((v[i    ] - mean) * inv * w[g * 8 + i    ] + b[g * 8 + i    ], 0.01f);
        o.y = lrelu((v[i + 1] - mean) * inv * w[g * 8 + i + 1] + b[g * 8 + i + 1], 0.01f);
        o.z = lrelu((v[i + 2] - mean) * inv * w[g * 8 + i + 2] + b[g * 8 + i + 2], 0.01f);
        o.w = lrelu((v[i + 3] - mean) * inv * w[g * 8 + i + 3] + b[g * 8 + i + 3], 0.01f);
        *(float4*)(op + i) = o;
    }
}

// ---------------- tf32 tensor-core GEMM: [n,K] @ [K,128] ---------------------
// 256 thr = 8 warps (4 in M x 2 in N); warp tile 32x64; mma m16n8k8.
// W converted to tf32 in smem once (pitch 136 = conflict-free B frags).
// A slab [128x16] tf32 (pitch 20). OUTH=1 -> fp16 out.
template <int K, int BIAS, int OUTH>
__global__ __launch_bounds__(256, 2)
void k_gemm_tc(const float* __restrict__ A, const float* __restrict__ W,
               const float* __restrict__ bias, float* __restrict__ out,
               __half* __restrict__ outh, int n) {
    extern __shared__ unsigned smemu[];
    unsigned* Ws = smemu;              // [K][136]
    unsigned* As = smemu + K * 136;    // [128][20]
    int tid = threadIdx.x;
    for (int i = tid; i < K * 128; i += 256) {
        int k = i >> 7, j = i & 127;
        Ws[k * 136 + j] = f2tf32(W[i]);
    }
    int lane = tid & 31, w = tid >> 5;
    int wm = (w & 3) * 32;
    int wn = (w >> 2) * 64;
    int r = lane >> 2, q = lane & 3;
    int arow = tid >> 1;
    int acol = (tid & 1) * 8;
    int tiles = (n + 127) >> 7;

    for (int tile = blockIdx.x; tile < tiles; tile += gridDim.x) {
        int m0 = tile << 7;
        float c[2][8][4];
        #pragma unroll
        for (int mt = 0; mt < 2; mt++)
            #pragma unroll
            for (int nt = 0; nt < 8; nt++)
                #pragma unroll
                for (int i = 0; i < 4; i++) c[mt][nt][i] = 0.f;

        for (int k0 = 0; k0 < K; k0 += 16) {
            __syncthreads();
            {
                int grow = m0 + arow;
                float4 v0 = make_float4(0.f,0.f,0.f,0.f), v1 = v0;
                if (grow < n) {
                    const float* ap = A + (size_t)grow * K + k0 + acol;
                    v0 = *(const float4*)ap;
                    v1 = *(const float4*)(ap + 4);
                }
                unsigned* d = As + arow * 20 + acol;
                d[0]=f2tf32(v0.x); d[1]=f2tf32(v0.y); d[2]=f2tf32(v0.z); d[3]=f2tf32(v0.w);
                d[4]=f2tf32(v1.x); d[5]=f2tf32(v1.y); d[6]=f2tf32(v1.z); d[7]=f2tf32(v1.w);
            }
            __syncthreads();
            #pragma unroll
            for (int kk = 0; kk < 16; kk += 8) {
                unsigned a[2][4];
                #pragma unroll
                for (int mt = 0; mt < 2; mt++) {
                    const unsigned* ap = As + (wm + mt * 16 + r) * 20 + kk + q;
                    a[mt][0] = ap[0];
                    a[mt][1] = ap[8 * 20];
                    a[mt][2] = ap[4];
                    a[mt][3] = ap[8 * 20 + 4];
                }
                #pragma unroll
                for (int nt = 0; nt < 8; nt++) {
                    unsigned b[2];
                    const unsigned* bp = Ws + (k0 + kk + q) * 136 + wn + nt * 8 + r;
                    b[0] = bp[0];
                    b[1] = bp[4 * 136];
                    mma_tf32(c[0][nt], a[0], b);
                    mma_tf32(c[1][nt], a[1], b);
                }
            }
        }
        #pragma unroll
        for (int mt = 0; mt < 2; mt++) {
            #pragma unroll
            for (int rr = 0; rr < 2; rr++) {
                int m = m0 + wm + mt * 16 + r + rr * 8;
                if (m < n) {
                    #pragma unroll
                    for (int nt = 0; nt < 8; nt++) {
                        int col = wn + nt * 8 + 2 * q;
                        float v0 = c[mt][nt][rr * 2 + 0];
                        float v1 = c[mt][nt][rr * 2 + 1];
                        if (BIAS) { v0 += bias[col]; v1 += bias[col + 1]; }
                        if (OUTH) {
                            *(__half2*)(outh + (size_t)m * 128 + col) = __floats2half2_rn(v0, v1);
                        } else {
                            *(float2*)(out + (size_t)m * 128 + col) = make_float2(v0, v1);
                        }
                    }
                }
            }
        }
    }
}

// ---------------- GCN conv (fp16 gather) + fused GN + LeakyReLU --------------
template <int BASEVEC, int OUTH>
__global__ void k_conv(const __half* __restrict__ srch, const float* __restrict__ basep,
                       float* __restrict__ dst, __half* __restrict__ dsth,
                       const float* __restrict__ gnw, const float* __restrict__ gnb, int n) {
    int gw = (blockIdx.x * blockDim.x + threadIdx.x) >> 5;
    int lane = threadIdx.x & 31;
    if (gw >= n) return;
    int c = gw;
    int beg = g_ptr[c], end = g_ptr[c + 1];
    float dc = g_dinv[c];
    float4 base = BASEVEC ? *(const float4*)(g_btt + lane * 4)
                          : *(const float4*)(basep + (size_t)c * 128 + lane * 4);
    float d2 = dc * dc;
    float4 acc;
    {
        const __half2* sp = (const __half2*)(srch + (size_t)c * 128 + lane * 4);
        float2 lo = __half22float2(sp[0]), hi = __half22float2(sp[1]);
        acc.x = base.x + d2 * lo.x; acc.y = base.y + d2 * lo.y;
        acc.z = base.z + d2 * hi.x; acc.w = base.w + d2 * hi.y;
    }
    for (int b0 = beg; b0 < end; b0 += 32) {
        int cnt = min(32, end - b0);
        int ridx = 0; float cw = 0.f;
        if (lane < cnt) { ridx = g_csr_r[b0 + lane]; cw = g_csr_c[b0 + lane]; }
        for (int j = 0; j < cnt; j++) {
            int r = __shfl_sync(0xffffffffu, ridx, j);
            float coef = __shfl_sync(0xffffffffu, cw, j);
            const __half2* sp = (const __half2*)(srch + (size_t)r * 128 + lane * 4);
            float2 lo = __half22float2(sp[0]), hi = __half22float2(sp[1]);
            acc.x += coef * lo.x; acc.y += coef * lo.y;
            acc.z += coef * hi.x; acc.w += coef * hi.y;
        }
    }
    float s  = acc.x + acc.y + acc.z + acc.w;
    float ss = acc.x * acc.x + acc.y * acc.y + acc.z * acc.z + acc.w * acc.w;
    s  += __shfl_xor_sync(0xffffffffu, s, 1);  ss += __shfl_xor_sync(0xffffffffu, ss, 1);
    s  += __shfl_xor_sync(0xffffffffu, s, 2);  ss += __shfl_xor_sync(0xffffffffu, ss, 2);
    float mean = s * (1.f / 16.f);
    float var  = ss * (1.f / 16.f) - mean * mean;
    float inv  = rsqrtf(var + 1e-5f);
    float4 wv = *(const float4*)(gnw + lane * 4);
    float4 bv = *(const float4*)(gnb + lane * 4);
    float4 o;
    o.x = lrelu((acc.x - mean) * inv * wv.x + bv.x, 0.01f);
    o.y = lrelu((acc.y - mean) * inv * wv.y + bv.y, 0.01f);
    o.z = lrelu((acc.z - mean) * inv * wv.z + bv.z, 0.01f);
    o.w = lrelu((acc.w - mean) * inv * wv.w + bv.w, 0.01f);
    *(float4*)(dst + (size_t)c * 128 + lane * 4) = o;
    if (OUTH) {
        __half2* hp = (__half2*)(dsth + (size_t)c * 128 + lane * 4);
        hp[0] = __floats2half2_rn(o.x, o.y);
        hp[1] = __floats2half2_rn(o.z, o.w);
    }
}

// ---------------- attention projections (fp16 ha) ----------------------------
__global__ void k_al(const float* __restrict__ asrc, const float* __restrict__ adst, int n) {
    int idx = blockIdx.x * blockDim.x + threadIdx.x;
    if (idx >= n * NH) return;
    int node = idx >> 2, h = idx & 3;
    const __half2* hp = (const __half2*)(g_hah + (size_t)node * COUT + h * 32);
    const float* sp = asrc + h * 32;
    const float* dp = adst + h * 32;
    float ds = 0.f, dd = 0.f;
    #pragma unroll
    for (int i = 0; i < 16; i++) {
        float2 v = __half22float2(hp[i]);
        ds += v.x * sp[i * 2] + v.y * sp[i * 2 + 1];
        dd += v.x * dp[i * 2] + v.y * dp[i * 2 + 1];
    }
    g_als[idx] = ds;
    g_ald[idx] = dd;
}

// ---------------- fused GAT: warp-per-node, online softmax, fp16 gather ------
__global__ __launch_bounds__(256)
void k_attn(const float* __restrict__ aedge, const float* __restrict__ ba,
            float* __restrict__ out, int n) {
    __shared__ float s_l[8][256];
    int gw = (blockIdx.x * blockDim.x + threadIdx.x) >> 5;
    int lane = threadIdx.x & 31;
    int wl = threadIdx.x >> 5;
    if (gw >= n) return;
    int c = gw;
    int beg = g_ptr[c], end = g_ptr[c + 1];
    int deg = end - beg;
    float4 ae = *(const float4*)aedge;
    float4 ad = *(const float4*)(g_ald + c * 4);
    float4 asl4 = *(const float4*)(g_als + c * 4);
    float fill = decf(g_fill);
    float l0 = lrelu(asl4.x + ad.x + ae.x * fill, 0.2f);
    float l1 = lrelu(asl4.y + ad.y + ae.y * fill, 0.2f);
    float l2 = lrelu(asl4.z + ad.z + ae.z * fill, 0.2f);
    float l3 = lrelu(asl4.w + ad.w + ae.w * fill, 0.2f);
    float m0 = -1e30f, m1 = -1e30f, m2 = -1e30f, m3 = -1e30f;
    float t0 = 0.f, t1 = 0.f, t2 = 0.f, t3 = 0.f;
    for (int i = beg + lane; i < end; i += 32) {
        int r = g_csr_r[i];
        float w = g_csr_w[i];
        float4 as = *(const float4*)(g_als + r * 4);
        float a0 = lrelu(as.x + ad.x + ae.x * w, 0.2f);
        float a1 = lrelu(as.y + ad.y + ae.y * w, 0.2f);
        float a2 = lrelu(as.z + ad.z + ae.z * w, 0.2f);
        float a3 = lrelu(as.w + ad.w + ae.w * w, 0.2f);
        int il = i - beg;
        if (il < 64) *(float4*)(&s_l[wl][il * 4]) = make_float4(a0, a1, a2, a3);
        float nm;
        nm = fmaxf(m0, a0); t0 = t0 * __expf(m0 - nm) + __expf(a0 - nm); m0 = nm;
        nm = fmaxf(m1, a1); t1 = t1 * __expf(m1 - nm) + __expf(a1 - nm); m1 = nm;
        nm = fmaxf(m2, a2); t2 = t2 * __expf(m2 - nm) + __expf(a2 - nm); m2 = nm;
        nm = fmaxf(m3, a3); t3 = t3 * __expf(m3 - nm) + __expf(a3 - nm); m3 = nm;
    }
    #pragma unroll
    for (int off = 16; off; off >>= 1) {
        float om, ot, nm;
        om = __shfl_xor_sync(0xffffffffu, m0, off); ot = __shfl_xor_sync(0xffffffffu, t0, off);
        nm = fmaxf(m0, om); t0 = t0 * __expf(m0 - nm) + ot * __expf(om - nm); m0 = nm;
        om = __shfl_xor_sync(0xffffffffu, m1, off); ot = __shfl_xor_sync(0xffffffffu, t1, off);
        nm = fmaxf(m1, om); t1 = t1 * __expf(m1 - nm) + ot * __expf(om - nm); m1 = nm;
        om = __shfl_xor_sync(0xffffffffu, m2, off); ot = __shfl_xor_sync(0xffffffffu, t2, off);
        nm = fmaxf(m2, om); t2 = t2 * __expf(m2 - nm) + ot * __expf(om - nm); m2 = nm;
        om = __shfl_xor_sync(0xffffffffu, m3, off); ot = __shfl_xor_sync(0xffffffffu, t3, off);
        nm = fmaxf(m3, om); t3 = t3 * __expf(m3 - nm) + ot * __expf(om - nm); m3 = nm;
    }
    float nm;
    nm = fmaxf(m0, l0); t0 = t0 * __expf(m0 - nm) + __expf(l0 - nm); m0 = nm;
    nm = fmaxf(m1, l1); t1 = t1 * __expf(m1 - nm) + __expf(l1 - nm); m1 = nm;
    nm = fmaxf(m2, l2); t2 = t2 * __expf(m2 - nm) + __expf(l2 - nm); m2 = nm;
    nm = fmaxf(m3, l3); t3 = t3 * __expf(m3 - nm) + __expf(l3 - nm); m3 = nm;
    float rs0 = 1.f / (t0 + 1e-16f), rs1 = 1.f / (t1 + 1e-16f);
    float rs2 = 1.f / (t2 + 1e-16f), rs3 = 1.f / (t3 + 1e-16f);
    int lim = min(deg, 64);
    for (int il = lane; il < lim; il += 32) {
        float4 lv = *(float4*)(&s_l[wl][il * 4]);
        lv.x = __expf(lv.x - m0); lv.y = __expf(lv.y - m1);
        lv.z = __expf(lv.z - m2); lv.w = __expf(lv.w - m3);
        *(float4*)(&s_l[wl][il * 4]) = lv;
    }
    __syncwarp();
    int h = lane >> 3;
    float rs  = (h == 0) ? rs0 : (h == 1) ? rs1 : (h == 2) ? rs2 : rs3;
    float mh  = (h == 0) ? m0  : (h == 1) ? m1  : (h == 2) ? m2  : m3;
    float aeh = (h == 0) ? ae.x : (h == 1) ? ae.y : (h == 2) ? ae.z : ae.w;
    float adh = (h == 0) ? ad.x : (h == 1) ? ad.y : (h == 2) ? ad.z : ad.w;
    float lh  = (h == 0) ? l0  : (h == 1) ? l1  : (h == 2) ? l2  : l3;
    float4 acc = *(const float4*)(ba + lane * 4);
    {
        float a_self = __expf(lh - mh) * rs;
        const __half2* vp = (const __half2*)(g_hah + (size_t)c * 128 + lane * 4);
        float2 lo = __half22float2(vp[0]), hi = __half22float2(vp[1]);
        acc.x += a_self * lo.x; acc.y += a_self * lo.y;
        acc.z += a_self * hi.x; acc.w += a_self * hi.y;
    }
    for (int b0 = beg; b0 < end; b0 += 32) {
        int cnt = min(32, end - b0);
        int ridx = 0; float wreg = 0.f;
        if (lane < cnt) { ridx = g_csr_r[b0 + lane]; wreg = g_csr_w[b0 + lane]; }
        for (int j = 0; j < cnt; j++) {
            int r = __shfl_sync(0xffffffffu, ridx, j);
            int il = b0 + j - beg;
            float e;
            if (il < 64) {
                e = s_l[wl][il * 4 + h];
            } else {
                float w = __shfl_sync(0xffffffffu, wreg, j);
                float asv = __ldg(g_als + r * 4 + h);
                e = __expf(lrelu(asv + adh + aeh * w, 0.2f) - mh);
            }
            float alpha = e * rs;
            const __half2* vp = (const __half2*)(g_hah + (size_t)r * 128 + lane * 4);
            float2 lo = __half22float2(vp[0]), hi = __half22float2(vp[1]);
            acc.x += alpha * lo.x; acc.y += alpha * lo.y;
            acc.z += alpha * hi.x; acc.w += alpha * hi.y;
        }
    }
    *(float4*)(out + (size_t)c * 128 + lane * 4) = acc;
}

// ---------------- launch -----------------------------------------------------
extern "C" void kernel_launch(void* const* d_in, const int* in_sizes, int n_in,
                              void* d_out, int out_size) {
    const float* x    = (const float*)d_in[0];
    const float* t    = (const float*)d_in[1];
    const int*   ei   = (const int*)  d_in[2];
    const float* ew   = (const float*)d_in[3];
    const float* gn0w = (const float*)d_in[4];
    const float* gn0b = (const float*)d_in[5];
    const float* W1   = (const float*)d_in[6];
    const float* b1   = (const float*)d_in[7];
    const float* gn1w = (const float*)d_in[8];
    const float* gn1b = (const float*)d_in[9];
    const float* W2   = (const float*)d_in[10];
    const float* b2   = (const float*)d_in[11];
    const float* Wres = (const float*)d_in[12];
    const float* tew  = (const float*)d_in[13];
    const float* teb  = (const float*)d_in[14];
    const float* gn2w = (const float*)d_in[15];
    const float* gn2b = (const float*)d_in[16];
    const float* Wa   = (const float*)d_in[17];
    const float* asrc = (const float*)d_in[18];
    const float* adst = (const float*)d_in[19];
    const float* aedg = (const float*)d_in[20];
    const float* ba   = (const float*)d_in[21];

    int n = in_sizes[0] / CIN;
    int E = in_sizes[3];
    const int* row  = ei;
    const int* colp = ei + E;
    float* out = (float*)d_out;

    const int SM64  = (64 * 136 + 128 * 20) * 4;    // 45056
    const int SM128 = (128 * 136 + 128 * 20) * 4;   // 79872

    static cudaStream_t s1 = nullptr, s2 = nullptr;
    static cudaEvent_t evInit = nullptr, evCSR = nullptr, evRes = nullptr;
    if (!s1) {
        cudaStreamCreateWithFlags(&s1, cudaStreamNonBlocking);
        cudaStreamCreateWithFlags(&s2, cudaStreamNonBlocking);
        cudaEventCreateWithFlags(&evInit, cudaEventDisableTiming);
        cudaEventCreateWithFlags(&evCSR,  cudaEventDisableTiming);
        cudaEventCreateWithFlags(&evRes,  cudaEventDisableTiming);
        cudaFuncSetAttribute(k_gemm_tc<CIN, 0, 1>,  cudaFuncAttributeMaxDynamicSharedMemorySize, SM64);
        cudaFuncSetAttribute(k_gemm_tc<CIN, 1, 0>,  cudaFuncAttributeMaxDynamicSharedMemorySize, SM64);
        cudaFuncSetAttribute(k_gemm_tc<COUT, 0, 1>, cudaFuncAttributeMaxDynamicSharedMemorySize, SM128);
    }

    float *p_a64, *p_a128, *p_res;
    __half *p_xwh, *p_hah;
    cudaGetSymbolAddress((void**)&p_a64,  g_a64);
    cudaGetSymbolAddress((void**)&p_xwh,  g_xwh);
    cudaGetSymbolAddress((void**)&p_hah,  g_hah);
    cudaGetSymbolAddress((void**)&p_a128, g_a128);
    cudaGetSymbolAddress((void**)&p_res,  g_res);

    const int T = 256;
    int n1   = n + 1;
    int gN   = (n + T - 1) / T;
    int gE   = (E + T - 1) / T;
    int gNG  = (n * 8 + T - 1) / T;
    int gNH_ = (n * NH + T - 1) / T;
    int gNW  = (n * 32 + T - 1) / T;
    int gSC  = (n1 + 255) / 256;
    const int GG = 296;

    k_init<<<gN, T>>>(teb, b1, n);
    cudaEventRecord(evInit, 0);

    // s1: CSR build
    cudaStreamWaitEvent(s1, evInit, 0);
    k_count<<<gE, T, 0, s1>>>(colp, ew, E);
    kScan1<<<gSC, 256, 0, s1>>>(n1);
    kScan2<<<1, 256, 0, s1>>>(gSC);
    kScan3<<<gSC, 256, 0, s1>>>(n1);

    // s2: residual GEMM (tf32 TC)
    cudaStreamWaitEvent(s2, evInit, 0);
    k_gemm_tc<CIN, 1, 0><<<GG, 256, SM64, s2>>>(x, Wres, b2, p_res, nullptr, n);
    cudaEventRecord(evRes, s2);

    k_place<<<gE, T, 0, s1>>>(row, colp, ew, E);
    cudaEventRecord(evCSR, s1);

    // main chain
    k_tt_partial<<<32, 128>>>(t, tew);
    k_gn0<<<gNG, T>>>(x, gn0w, gn0b, p_a64, n);
    k_gemm_tc<CIN, 0, 1><<<GG, 256, SM64>>>(p_a64, W1, nullptr, nullptr, p_xwh, n);
    cudaStreamWaitEvent(0, evCSR, 0);
    k_conv<1, 0><<<gNW, T>>>(p_xwh, nullptr, p_a128, nullptr, gn1w, gn1b, n);

    k_gemm_tc<COUT, 0, 1><<<GG, 256, SM128>>>(p_a128, W2, nullptr, nullptr, p_xwh, n);
    cudaStreamWaitEvent(0, evRes, 0);
    k_conv<0, 0><<<gNW, T>>>(p_xwh, p_res, p_a128, nullptr, gn2w, gn2b, n);

    k_gemm_tc<COUT, 0, 1><<<GG, 256, SM128>>>(p_a128, Wa, nullptr, nullptr, p_hah, n);
    k_al<<<gNH_, T>>>(asrc, adst, n);
    k_attn<<<gNW, T>>>(aedg, ba, out, n);
}

// round 7
// speedup vs baseline: 3.2489x; 1.0506x over previous
#include <cuda_runtime.h>
#include <cuda_fp16.h>
#include <math.h>

#define NMAX 50000
#define EMAX 800000
#define CIN 64
#define COUT 128
#define NH 4

// ---------------- scratch ----------------------------------------------------
__device__ float    g_deg[NMAX];
__device__ float    g_dinv[NMAX];
__device__ float    g_btt[COUT];
__device__ unsigned g_fill;
__device__ int      g_count[NMAX];
__device__ int      g_ptr[NMAX + 1];
__device__ int      g_cursor[NMAX];
__device__ int      g_part[256];
__device__ int      g_pscan[256];
__device__ int      g_csr_r[EMAX];
__device__ float    g_csr_w[EMAX];
__device__ float    g_csr_c[EMAX];
__device__ __half   g_xwh [NMAX * COUT];   // fp16 gather source (GCN)
__device__ __half   g_hah [NMAX * COUT];   // fp16 attention features
__device__ float    g_a128[NMAX * COUT];
__device__ float    g_res [NMAX * COUT];
__device__ float    g_als [NMAX * NH];
__device__ float    g_ald [NMAX * NH];

// ---------------- helpers ----------------------------------------------------
__device__ __forceinline__ float lrelu(float v, float s) { return v > 0.f ? v : s * v; }
__device__ __forceinline__ unsigned encf(float f) {
    unsigned u = __float_as_uint(f);
    return (u & 0x80000000u) ? ~u : (u | 0x80000000u);
}
__device__ __forceinline__ float decf(unsigned u) {
    return (u & 0x80000000u) ? __uint_as_float(u & 0x7fffffffu) : __uint_as_float(~u);
}
__device__ __forceinline__ unsigned f2tf32(float f) {
    unsigned u; asm("cvt.rna.tf32.f32 %0, %1;" : "=r"(u) : "f"(f)); return u;
}
__device__ __forceinline__ void mma_tf32(float* c, const unsigned* a, const unsigned* b) {
    asm("mma.sync.aligned.m16n8k8.row.col.f32.tf32.tf32.f32 "
        "{%0,%1,%2,%3}, {%4,%5,%6,%7}, {%8,%9}, {%0,%1,%2,%3};"
        : "+f"(c[0]), "+f"(c[1]), "+f"(c[2]), "+f"(c[3])
        : "r"(a[0]), "r"(a[1]), "r"(a[2]), "r"(a[3]), "r"(b[0]), "r"(b[1]));
}

// ---------------- setup ------------------------------------------------------
__global__ void k_init(const float* __restrict__ teb, const float* __restrict__ b1, int n) {
    int i = blockIdx.x * blockDim.x + threadIdx.x;
    if (i == 0) g_fill = 0u;
    if (i < COUT) g_btt[i] = teb[i] + b1[i];
    if (i < n) { g_deg[i] = 1.0f; g_count[i] = 0; }
}

__global__ void k_count(const int* __restrict__ col, const float* __restrict__ ew, int E) {
    int e = blockIdx.x * blockDim.x + threadIdx.x;
    float w = 0.f;
    if (e < E) {
        w = ew[e];
        int c = col[e];
        atomicAdd(&g_count[c], 1);
        atomicAdd(&g_deg[c], w);
    }
    #pragma unroll
    for (int off = 16; off; off >>= 1) w = fmaxf(w, __shfl_down_sync(0xffffffffu, w, off));
    __shared__ float sm[8];
    int lane = threadIdx.x & 31, wid = threadIdx.x >> 5;
    if (lane == 0) sm[wid] = w;
    __syncthreads();
    if (threadIdx.x == 0) {
        float m = sm[0];
        #pragma unroll
        for (int i = 1; i < 8; i++) m = fmaxf(m, sm[i]);
        atomicMax(&g_fill, encf(m));
    }
}

__global__ void kScan1(int n1) {
    __shared__ int sm[256];
    int tid = threadIdx.x;
    int i = blockIdx.x * 256 + tid;
    int x = (i < n1 - 1) ? g_count[i] : 0;
    sm[tid] = x;
    __syncthreads();
    #pragma unroll
    for (int off = 1; off < 256; off <<= 1) {
        int v = (tid >= off) ? sm[tid - off] : 0;
        __syncthreads();
        sm[tid] += v;
        __syncthreads();
    }
    if (i < n1) g_ptr[i] = sm[tid] - x;
    if (tid == 255) g_part[blockIdx.x] = sm[255];
}

__global__ void kScan2(int nb) {
    __shared__ int sm[256];
    int tid = threadIdx.x;
    int x = (tid < nb) ? g_part[tid] : 0;
    sm[tid] = x;
    __syncthreads();
    #pragma unroll
    for (int off = 1; off < 256; off <<= 1) {
        int v = (tid >= off) ? sm[tid - off] : 0;
        __syncthreads();
        sm[tid] += v;
        __syncthreads();
    }
    g_pscan[tid] = sm[tid] - x;
}

__global__ void kScan3(int n1) {
    int i = blockIdx.x * blockDim.x + threadIdx.x;
    if (i < n1) {
        int v = g_ptr[i] + g_pscan[i >> 8];
        g_ptr[i] = v;
        if (i < n1 - 1) {
            g_cursor[i] = v;
            g_dinv[i] = rsqrtf(g_deg[i]);
        }
    }
}

__global__ void k_place(const int* __restrict__ row, const int* __restrict__ col,
                        const float* __restrict__ ew, int E) {
    int e = blockIdx.x * blockDim.x + threadIdx.x;
    if (e >= E) return;
    int c = col[e];
    int r = row[e];
    float w = ew[e];
    int slot = atomicAdd(&g_cursor[c], 1);
    g_csr_r[slot] = r;
    g_csr_w[slot] = w;
    g_csr_c[slot] = g_dinv[r] * w * g_dinv[c];
}

__global__ void k_tt_partial(const float* __restrict__ t, const float* __restrict__ tew) {
    int j = threadIdx.x;
    int k0 = blockIdx.x * 16;
    float acc = 0.f;
    #pragma unroll
    for (int k = 0; k < 16; k++) acc += lrelu(t[k0 + k], 0.01f) * tew[(k0 + k) * COUT + j];
    atomicAdd(&g_btt[j], acc);
}

// ---------------- tf32 tensor-core GEMM: [n,K] @ [K,128] ---------------------
// 256 thr = 8 warps (4 in M x 2 in N); warp tile 32x64; mma m16n8k8.
// GN0=1: apply GroupNorm(8ch groups)+LeakyReLU to A during slab load (K=64).
// AL=1: epilogue computes per-head src/dst attention projections into g_als/g_ald.
// OUTH=1 -> fp16 out.
template <int K, int BIAS, int OUTH, int GN0, int AL>
__global__ __launch_bounds__(256, 2)
void k_gemm_tc(const float* __restrict__ A, const float* __restrict__ W,
               const float* __restrict__ bias, float* __restrict__ out,
               __half* __restrict__ outh, const float* __restrict__ gnw,
               const float* __restrict__ gnb, const float* __restrict__ asrc,
               const float* __restrict__ adst, int n) {
    extern __shared__ unsigned smemu[];
    unsigned* Ws = smemu;              // [K][136]
    unsigned* As = smemu + K * 136;    // [128][20]
    int tid = threadIdx.x;
    for (int i = tid; i < K * 128; i += 256) {
        int k = i >> 7, j = i & 127;
        Ws[k * 136 + j] = f2tf32(W[i]);
    }
    int lane = tid & 31, w = tid >> 5;
    int wm = (w & 3) * 32;
    int wn = (w >> 2) * 64;
    int r = lane >> 2, q = lane & 3;
    int arow = tid >> 1;
    int acol = (tid & 1) * 8;
    int tiles = (n + 127) >> 7;

    // AL: preload attention vectors for this lane's columns (uniform over tiles)
    float asr[2][8], adr[2][8];
    int hbase = wn >> 5;
    if (AL) {
        #pragma unroll
        for (int hh = 0; hh < 2; hh++)
            #pragma unroll
            for (int j = 0; j < 4; j++)
                #pragma unroll
                for (int i2 = 0; i2 < 2; i2++) {
                    int idx = (hbase + hh) * 32 + j * 8 + 2 * q + i2;
                    asr[hh][j * 2 + i2] = __ldg(asrc + idx);
                    adr[hh][j * 2 + i2] = __ldg(adst + idx);
                }
    }

    for (int tile = blockIdx.x; tile < tiles; tile += gridDim.x) {
        int m0 = tile << 7;
        float c[2][8][4];
        #pragma unroll
        for (int mt = 0; mt < 2; mt++)
            #pragma unroll
            for (int nt = 0; nt < 8; nt++)
                #pragma unroll
                for (int i = 0; i < 4; i++) c[mt][nt][i] = 0.f;

        for (int k0 = 0; k0 < K; k0 += 16) {
            __syncthreads();
            {
                int grow = m0 + arow;
                float4 v0 = make_float4(0.f,0.f,0.f,0.f), v1 = v0;
                if (grow < n) {
                    const float* ap = A + (size_t)grow * K + k0 + acol;
                    v0 = *(const float4*)ap;
                    v1 = *(const float4*)(ap + 4);
                }
                float v[8] = {v0.x, v0.y, v0.z, v0.w, v1.x, v1.y, v1.z, v1.w};
                if (GN0) {
                    // 8 contiguous channels = exactly one GN group (C=64, G=8)
                    float s = 0.f, ss = 0.f;
                    #pragma unroll
                    for (int i = 0; i < 8; i++) { s += v[i]; ss += v[i] * v[i]; }
                    float mean = s * 0.125f;
                    float var  = ss * 0.125f - mean * mean;
                    float inv  = rsqrtf(var + 1e-5f);
                    int gb = k0 + acol;
                    #pragma unroll
                    for (int i = 0; i < 8; i++)
                        v[i] = lrelu((v[i] - mean) * inv * __ldg(gnw + gb + i)
                                     + __ldg(gnb + gb + i), 0.01f);
                }
                unsigned* d = As + arow * 20 + acol;
                #pragma unroll
                for (int i = 0; i < 8; i++) d[i] = f2tf32(v[i]);
            }
            __syncthreads();
            #pragma unroll
            for (int kk = 0; kk < 16; kk += 8) {
                unsigned a[2][4];
                #pragma unroll
                for (int mt = 0; mt < 2; mt++) {
                    const unsigned* ap = As + (wm + mt * 16 + r) * 20 + kk + q;
                    a[mt][0] = ap[0];
                    a[mt][1] = ap[8 * 20];
                    a[mt][2] = ap[4];
                    a[mt][3] = ap[8 * 20 + 4];
                }
                #pragma unroll
                for (int nt = 0; nt < 8; nt++) {
                    unsigned b[2];
                    const unsigned* bp = Ws + (k0 + kk + q) * 136 + wn + nt * 8 + r;
                    b[0] = bp[0];
                    b[1] = bp[4 * 136];
                    mma_tf32(c[0][nt], a[0], b);
                    mma_tf32(c[1][nt], a[1], b);
                }
            }
        }
        #pragma unroll
        for (int mt = 0; mt < 2; mt++) {
            #pragma unroll
            for (int rr = 0; rr < 2; rr++) {
                int m = m0 + wm + mt * 16 + r + rr * 8;
                if (m < n) {
                    #pragma unroll
                    for (int nt = 0; nt < 8; nt++) {
                        int col = wn + nt * 8 + 2 * q;
                        float v0 = c[mt][nt][rr * 2 + 0];
                        float v1 = c[mt][nt][rr * 2 + 1];
                        if (BIAS) { v0 += bias[col]; v1 += bias[col + 1]; }
                        if (OUTH) {
                            *(__half2*)(outh + (size_t)m * 128 + col) = __floats2half2_rn(v0, v1);
                        } else {
                            *(float2*)(out + (size_t)m * 128 + col) = make_float2(v0, v1);
                        }
                    }
                }
                if (AL) {
                    float sA0 = 0.f, sA1 = 0.f, sD0 = 0.f, sD1 = 0.f;
                    #pragma unroll
                    for (int j = 0; j < 4; j++)
                        #pragma unroll
                        for (int i2 = 0; i2 < 2; i2++) {
                            float c0 = c[mt][j][rr * 2 + i2];
                            float c1 = c[mt][4 + j][rr * 2 + i2];
                            sA0 += c0 * asr[0][j * 2 + i2];
                            sD0 += c0 * adr[0][j * 2 + i2];
                            sA1 += c1 * asr[1][j * 2 + i2];
                            sD1 += c1 * adr[1][j * 2 + i2];
                        }
                    sA0 += __shfl_xor_sync(0xffffffffu, sA0, 1);
                    sA0 += __shfl_xor_sync(0xffffffffu, sA0, 2);
                    sA1 += __shfl_xor_sync(0xffffffffu, sA1, 1);
                    sA1 += __shfl_xor_sync(0xffffffffu, sA1, 2);
                    sD0 += __shfl_xor_sync(0xffffffffu, sD0, 1);
                    sD0 += __shfl_xor_sync(0xffffffffu, sD0, 2);
                    sD1 += __shfl_xor_sync(0xffffffffu, sD1, 1);
                    sD1 += __shfl_xor_sync(0xffffffffu, sD1, 2);
                    if (q == 0 && m < n) {
                        g_als[m * 4 + hbase]     = sA0;
                        g_als[m * 4 + hbase + 1] = sA1;
                        g_ald[m * 4 + hbase]     = sD0;
                        g_ald[m * 4 + hbase + 1] = sD1;
                    }
                }
            }
        }
    }
}

// ---------------- GCN conv (fp16 gather) + fused GN + LeakyReLU --------------
template <int BASEVEC>
__global__ void k_conv(const __half* __restrict__ srch, const float* __restrict__ basep,
                       float* __restrict__ dst,
                       const float* __restrict__ gnw, const float* __restrict__ gnb, int n) {
    int gw = (blockIdx.x * blockDim.x + threadIdx.x) >> 5;
    int lane = threadIdx.x & 31;
    if (gw >= n) return;
    int c = gw;
    int beg = g_ptr[c], end = g_ptr[c + 1];
    float dc = g_dinv[c];
    float4 base = BASEVEC ? *(const float4*)(g_btt + lane * 4)
                          : *(const float4*)(basep + (size_t)c * 128 + lane * 4);
    float d2 = dc * dc;
    float4 acc;
    {
        const __half2* sp = (const __half2*)(srch + (size_t)c * 128 + lane * 4);
        float2 lo = __half22float2(sp[0]), hi = __half22float2(sp[1]);
        acc.x = base.x + d2 * lo.x; acc.y = base.y + d2 * lo.y;
        acc.z = base.z + d2 * hi.x; acc.w = base.w + d2 * hi.y;
    }
    for (int b0 = beg; b0 < end; b0 += 32) {
        int cnt = min(32, end - b0);
        int ridx = 0; float cw = 0.f;
        if (lane < cnt) { ridx = g_csr_r[b0 + lane]; cw = g_csr_c[b0 + lane]; }
        for (int j = 0; j < cnt; j++) {
            int r = __shfl_sync(0xffffffffu, ridx, j);
            float coef = __shfl_sync(0xffffffffu, cw, j);
            const __half2* sp = (const __half2*)(srch + (size_t)r * 128 + lane * 4);
            float2 lo = __half22float2(sp[0]), hi = __half22float2(sp[1]);
            acc.x += coef * lo.x; acc.y += coef * lo.y;
            acc.z += coef * hi.x; acc.w += coef * hi.y;
        }
    }
    float s  = acc.x + acc.y + acc.z + acc.w;
    float ss = acc.x * acc.x + acc.y * acc.y + acc.z * acc.z + acc.w * acc.w;
    s  += __shfl_xor_sync(0xffffffffu, s, 1);  ss += __shfl_xor_sync(0xffffffffu, ss, 1);
    s  += __shfl_xor_sync(0xffffffffu, s, 2);  ss += __shfl_xor_sync(0xffffffffu, ss, 2);
    float mean = s * (1.f / 16.f);
    float var  = ss * (1.f / 16.f) - mean * mean;
    float inv  = rsqrtf(var + 1e-5f);
    float4 wv = *(const float4*)(gnw + lane * 4);
    float4 bv = *(const float4*)(gnb + lane * 4);
    float4 o;
    o.x = lrelu((acc.x - mean) * inv * wv.x + bv.x, 0.01f);
    o.y = lrelu((acc.y - mean) * inv * wv.y + bv.y, 0.01f);
    o.z = lrelu((acc.z - mean) * inv * wv.z + bv.z, 0.01f);
    o.w = lrelu((acc.w - mean) * inv * wv.w + bv.w, 0.01f);
    *(float4*)(dst + (size_t)c * 128 + lane * 4) = o;
}

// ---------------- fused GAT: warp-per-node, online softmax, fp16 gather ------
__global__ __launch_bounds__(256)
void k_attn(const float* __restrict__ aedge, const float* __restrict__ ba,
            float* __restrict__ out, int n) {
    __shared__ float s_l[8][256];
    int gw = (blockIdx.x * blockDim.x + threadIdx.x) >> 5;
    int lane = threadIdx.x & 31;
    int wl = threadIdx.x >> 5;
    if (gw >= n) return;
    int c = gw;
    int beg = g_ptr[c], end = g_ptr[c + 1];
    int deg = end - beg;
    float4 ae = *(const float4*)aedge;
    float4 ad = *(const float4*)(g_ald + c * 4);
    float4 asl4 = *(const float4*)(g_als + c * 4);
    float fill = decf(g_fill);
    float l0 = lrelu(asl4.x + ad.x + ae.x * fill, 0.2f);
    float l1 = lrelu(asl4.y + ad.y + ae.y * fill, 0.2f);
    float l2 = lrelu(asl4.z + ad.z + ae.z * fill, 0.2f);
    float l3 = lrelu(asl4.w + ad.w + ae.w * fill, 0.2f);
    float m0 = -1e30f, m1 = -1e30f, m2 = -1e30f, m3 = -1e30f;
    float t0 = 0.f, t1 = 0.f, t2 = 0.f, t3 = 0.f;
    for (int i = beg + lane; i < end; i += 32) {
        int r = g_csr_r[i];
        float w = g_csr_w[i];
        float4 as = *(const float4*)(g_als + r * 4);
        float a0 = lrelu(as.x + ad.x + ae.x * w, 0.2f);
        float a1 = lrelu(as.y + ad.y + ae.y * w, 0.2f);
        float a2 = lrelu(as.z + ad.z + ae.z * w, 0.2f);
        float a3 = lrelu(as.w + ad.w + ae.w * w, 0.2f);
        int il = i - beg;
        if (il < 64) *(float4*)(&s_l[wl][il * 4]) = make_float4(a0, a1, a2, a3);
        float nm;
        nm = fmaxf(m0, a0); t0 = t0 * __expf(m0 - nm) + __expf(a0 - nm); m0 = nm;
        nm = fmaxf(m1, a1); t1 = t1 * __expf(m1 - nm) + __expf(a1 - nm); m1 = nm;
        nm = fmaxf(m2, a2); t2 = t2 * __expf(m2 - nm) + __expf(a2 - nm); m2 = nm;
        nm = fmaxf(m3, a3); t3 = t3 * __expf(m3 - nm) + __expf(a3 - nm); m3 = nm;
    }
    #pragma unroll
    for (int off = 16; off; off >>= 1) {
        float om, ot, nm;
        om = __shfl_xor_sync(0xffffffffu, m0, off); ot = __shfl_xor_sync(0xffffffffu, t0, off);
        nm = fmaxf(m0, om); t0 = t0 * __expf(m0 - nm) + ot * __expf(om - nm); m0 = nm;
        om = __shfl_xor_sync(0xffffffffu, m1, off); ot = __shfl_xor_sync(0xffffffffu, t1, off);
        nm = fmaxf(m1, om); t1 = t1 * __expf(m1 - nm) + ot * __expf(om - nm); m1 = nm;
        om = __shfl_xor_sync(0xffffffffu, m2, off); ot = __shfl_xor_sync(0xffffffffu, t2, off);
        nm = fmaxf(m2, om); t2 = t2 * __expf(m2 - nm) + ot * __expf(om - nm); m2 = nm;
        om = __shfl_xor_sync(0xffffffffu, m3, off); ot = __shfl_xor_sync(0xffffffffu, t3, off);
        nm = fmaxf(m3, om); t3 = t3 * __expf(m3 - nm) + ot * __expf(om - nm); m3 = nm;
    }
    float nm;
    nm = fmaxf(m0, l0); t0 = t0 * __expf(m0 - nm) + __expf(l0 - nm); m0 = nm;
    nm = fmaxf(m1, l1); t1 = t1 * __expf(m1 - nm) + __expf(l1 - nm); m1 = nm;
    nm = fmaxf(m2, l2); t2 = t2 * __expf(m2 - nm) + __expf(l2 - nm); m2 = nm;
    nm = fmaxf(m3, l3); t3 = t3 * __expf(m3 - nm) + __expf(l3 - nm); m3 = nm;
    float rs0 = 1.f / (t0 + 1e-16f), rs1 = 1.f / (t1 + 1e-16f);
    float rs2 = 1.f / (t2 + 1e-16f), rs3 = 1.f / (t3 + 1e-16f);
    int lim = min(deg, 64);
    for (int il = lane; il < lim; il += 32) {
        float4 lv = *(float4*)(&s_l[wl][il * 4]);
        lv.x = __expf(lv.x - m0); lv.y = __expf(lv.y - m1);
        lv.z = __expf(lv.z - m2); lv.w = __expf(lv.w - m3);
        *(float4*)(&s_l[wl][il * 4]) = lv;
    }
    __syncwarp();
    int h = lane >> 3;
    float rs  = (h == 0) ? rs0 : (h == 1) ? rs1 : (h == 2) ? rs2 : rs3;
    float mh  = (h == 0) ? m0  : (h == 1) ? m1  : (h == 2) ? m2  : m3;
    float aeh = (h == 0) ? ae.x : (h == 1) ? ae.y : (h == 2) ? ae.z : ae.w;
    float adh = (h == 0) ? ad.x : (h == 1) ? ad.y : (h == 2) ? ad.z : ad.w;
    float lh  = (h == 0) ? l0  : (h == 1) ? l1  : (h == 2) ? l2  : l3;
    float4 acc = *(const float4*)(ba + lane * 4);
    {
        float a_self = __expf(lh - mh) * rs;
        const __half2* vp = (const __half2*)(g_hah + (size_t)c * 128 + lane * 4);
        float2 lo = __half22float2(vp[0]), hi = __half22float2(vp[1]);
        acc.x += a_self * lo.x; acc.y += a_self * lo.y;
        acc.z += a_self * hi.x; acc.w += a_self * hi.y;
    }
    for (int b0 = beg; b0 < end; b0 += 32) {
        int cnt = min(32, end - b0);
        int ridx = 0; float wreg = 0.f;
        if (lane < cnt) { ridx = g_csr_r[b0 + lane]; wreg = g_csr_w[b0 + lane]; }
        for (int j = 0; j < cnt; j++) {
            int r = __shfl_sync(0xffffffffu, ridx, j);
            int il = b0 + j - beg;
            float e;
            if (il < 64) {
                e = s_l[wl][il * 4 + h];
            } else {
                float w = __shfl_sync(0xffffffffu, wreg, j);
                float asv = __ldg(g_als + r * 4 + h);
                e = __expf(lrelu(asv + adh + aeh * w, 0.2f) - mh);
            }
            float alpha = e * rs;
            const __half2* vp = (const __half2*)(g_hah + (size_t)r * 128 + lane * 4);
            float2 lo = __half22float2(vp[0]), hi = __half22float2(vp[1]);
            acc.x += alpha * lo.x; acc.y += alpha * lo.y;
            acc.z += alpha * hi.x; acc.w += alpha * hi.y;
        }
    }
    *(float4*)(out + (size_t)c * 128 + lane * 4) = acc;
}

// ---------------- launch -----------------------------------------------------
extern "C" void kernel_launch(void* const* d_in, const int* in_sizes, int n_in,
                              void* d_out, int out_size) {
    const float* x    = (const float*)d_in[0];
    const float* t    = (const float*)d_in[1];
    const int*   ei   = (const int*)  d_in[2];
    const float* ew   = (const float*)d_in[3];
    const float* gn0w = (const float*)d_in[4];
    const float* gn0b = (const float*)d_in[5];
    const float* W1   = (const float*)d_in[6];
    const float* b1   = (const float*)d_in[7];
    const float* gn1w = (const float*)d_in[8];
    const float* gn1b = (const float*)d_in[9];
    const float* W2   = (const float*)d_in[10];
    const float* b2   = (const float*)d_in[11];
    const float* Wres = (const float*)d_in[12];
    const float* tew  = (const float*)d_in[13];
    const float* teb  = (const float*)d_in[14];
    const float* gn2w = (const float*)d_in[15];
    const float* gn2b = (const float*)d_in[16];
    const float* Wa   = (const float*)d_in[17];
    const float* asrc = (const float*)d_in[18];
    const float* adst = (const float*)d_in[19];
    const float* aedg = (const float*)d_in[20];
    const float* ba   = (const float*)d_in[21];

    int n = in_sizes[0] / CIN;
    int E = in_sizes[3];
    const int* row  = ei;
    const int* colp = ei + E;
    float* out = (float*)d_out;

    const int SM64  = (64 * 136 + 128 * 20) * 4;    // 45056
    const int SM128 = (128 * 136 + 128 * 20) * 4;   // 79872

    static cudaStream_t s1 = nullptr, s2 = nullptr;
    static cudaEvent_t evInit = nullptr, evCSR = nullptr, evAux = nullptr;
    if (!s1) {
        cudaStreamCreateWithFlags(&s1, cudaStreamNonBlocking);
        cudaStreamCreateWithFlags(&s2, cudaStreamNonBlocking);
        cudaEventCreateWithFlags(&evInit, cudaEventDisableTiming);
        cudaEventCreateWithFlags(&evCSR,  cudaEventDisableTiming);
        cudaEventCreateWithFlags(&evAux,  cudaEventDisableTiming);
        cudaFuncSetAttribute(k_gemm_tc<CIN, 0, 1, 1, 0>,  cudaFuncAttributeMaxDynamicSharedMemorySize, SM64);
        cudaFuncSetAttribute(k_gemm_tc<CIN, 1, 0, 0, 0>,  cudaFuncAttributeMaxDynamicSharedMemorySize, SM64);
        cudaFuncSetAttribute(k_gemm_tc<COUT, 0, 1, 0, 0>, cudaFuncAttributeMaxDynamicSharedMemorySize, SM128);
        cudaFuncSetAttribute(k_gemm_tc<COUT, 0, 1, 0, 1>, cudaFuncAttributeMaxDynamicSharedMemorySize, SM128);
    }

    float *p_a128, *p_res;
    __half *p_xwh, *p_hah;
    cudaGetSymbolAddress((void**)&p_xwh,  g_xwh);
    cudaGetSymbolAddress((void**)&p_hah,  g_hah);
    cudaGetSymbolAddress((void**)&p_a128, g_a128);
    cudaGetSymbolAddress((void**)&p_res,  g_res);

    const int T = 256;
    int n1   = n + 1;
    int gN   = (n + T - 1) / T;
    int gE   = (E + T - 1) / T;
    int gNW  = (n * 32 + T - 1) / T;
    int gSC  = (n1 + 255) / 256;
    const int GG = 296;

    k_init<<<gN, T>>>(teb, b1, n);
    cudaEventRecord(evInit, 0);

    // s1: CSR build
    cudaStreamWaitEvent(s1, evInit, 0);
    k_count<<<gE, T, 0, s1>>>(colp, ew, E);
    kScan1<<<gSC, 256, 0, s1>>>(n1);
    kScan2<<<1, 256, 0, s1>>>(gSC);
    kScan3<<<gSC, 256, 0, s1>>>(n1);
    k_place<<<gE, T, 0, s1>>>(row, colp, ew, E);
    cudaEventRecord(evCSR, s1);

    // s2: residual GEMM + time embed (both off critical path)
    cudaStreamWaitEvent(s2, evInit, 0);
    k_gemm_tc<CIN, 1, 0, 0, 0><<<GG, 256, SM64, s2>>>(x, Wres, b2, p_res, nullptr,
                                                      nullptr, nullptr, nullptr, nullptr, n);
    k_tt_partial<<<32, 128, 0, s2>>>(t, tew);
    cudaEventRecord(evAux, s2);

    // main chain: GEMM1 (fused GN0+lrelu on A)
    k_gemm_tc<CIN, 0, 1, 1, 0><<<GG, 256, SM64>>>(x, W1, nullptr, nullptr, p_xwh,
                                                  gn0w, gn0b, nullptr, nullptr, n);
    cudaStreamWaitEvent(0, evCSR, 0);
    cudaStreamWaitEvent(0, evAux, 0);
    k_conv<1><<<gNW, T>>>(p_xwh, nullptr, p_a128, gn1w, gn1b, n);

    k_gemm_tc<COUT, 0, 1, 0, 0><<<GG, 256, SM128>>>(p_a128, W2, nullptr, nullptr, p_xwh,
                                                    nullptr, nullptr, nullptr, nullptr, n);
    k_conv<0><<<gNW, T>>>(p_xwh, p_res, p_a128, gn2w, gn2b, n);

    // GEMM3 with fused attention projections
    k_gemm_tc<COUT, 0, 1, 0, 1><<<GG, 256, SM128>>>(p_a128, Wa, nullptr, nullptr, p_hah,
                                                    nullptr, nullptr, asrc, adst, n);
    k_attn<<<gNW, T>>>(aedg, ba, out, n);
}

// round 8
// speedup vs baseline: 3.3775x; 1.0396x over previous
#include <cuda_runtime.h>
#include <cuda_fp16.h>
#include <math.h>

#define NMAX 50000
#define EMAX 800000
#define CIN 64
#define COUT 128
#define NH 4

// ---------------- scratch ----------------------------------------------------
__device__ float    g_deg[NMAX];
__device__ float    g_dinv[NMAX];
__device__ float    g_btt[COUT];
__device__ unsigned g_fill;
__device__ int      g_count[NMAX];
__device__ int      g_ptr[NMAX + 1];
__device__ int      g_cursor[NMAX];
__device__ int      g_part[256];
__device__ int      g_pscan[256];
__device__ int      g_csr_r[EMAX];
__device__ float    g_csr_w[EMAX];
__device__ float    g_csr_c[EMAX];
__device__ __half   g_xwh [NMAX * COUT];   // fp16 gather source (GCN)
__device__ __half   g_hah [NMAX * COUT];   // fp16 attention features
__device__ float    g_a128[NMAX * COUT];
__device__ float    g_res [NMAX * COUT];
__device__ float    g_als [NMAX * NH];
__device__ float    g_ald [NMAX * NH];

// ---------------- helpers ----------------------------------------------------
__device__ __forceinline__ float lrelu(float v, float s) { return v > 0.f ? v : s * v; }
__device__ __forceinline__ unsigned encf(float f) {
    unsigned u = __float_as_uint(f);
    return (u & 0x80000000u) ? ~u : (u | 0x80000000u);
}
__device__ __forceinline__ float decf(unsigned u) {
    return (u & 0x80000000u) ? __uint_as_float(u & 0x7fffffffu) : __uint_as_float(~u);
}
__device__ __forceinline__ unsigned f2tf32(float f) {
    unsigned u; asm("cvt.rna.tf32.f32 %0, %1;" : "=r"(u) : "f"(f)); return u;
}
__device__ __forceinline__ void mma_tf32(float* c, const unsigned* a, const unsigned* b) {
    asm("mma.sync.aligned.m16n8k8.row.col.f32.tf32.tf32.f32 "
        "{%0,%1,%2,%3}, {%4,%5,%6,%7}, {%8,%9}, {%0,%1,%2,%3};"
        : "+f"(c[0]), "+f"(c[1]), "+f"(c[2]), "+f"(c[3])
        : "r"(a[0]), "r"(a[1]), "r"(a[2]), "r"(a[3]), "r"(b[0]), "r"(b[1]));
}

// ---------------- setup ------------------------------------------------------
__global__ void k_init(const float* __restrict__ teb, const float* __restrict__ b1, int n) {
    int i = blockIdx.x * blockDim.x + threadIdx.x;
    if (i == 0) g_fill = 0u;
    if (i < COUT) g_btt[i] = teb[i] + b1[i];
    if (i < n) { g_deg[i] = 1.0f; g_count[i] = 0; }
}

__global__ void k_count(const int* __restrict__ col, const float* __restrict__ ew, int E) {
    int e = blockIdx.x * blockDim.x + threadIdx.x;
    float w = 0.f;
    if (e < E) {
        w = ew[e];
        int c = col[e];
        atomicAdd(&g_count[c], 1);
        atomicAdd(&g_deg[c], w);
    }
    #pragma unroll
    for (int off = 16; off; off >>= 1) w = fmaxf(w, __shfl_down_sync(0xffffffffu, w, off));
    __shared__ float sm[8];
    int lane = threadIdx.x & 31, wid = threadIdx.x >> 5;
    if (lane == 0) sm[wid] = w;
    __syncthreads();
    if (threadIdx.x == 0) {
        float m = sm[0];
        #pragma unroll
        for (int i = 1; i < 8; i++) m = fmaxf(m, sm[i]);
        atomicMax(&g_fill, encf(m));
    }
}

__global__ void kScan1(int n1) {
    __shared__ int sm[256];
    int tid = threadIdx.x;
    int i = blockIdx.x * 256 + tid;
    int x = (i < n1 - 1) ? g_count[i] : 0;
    sm[tid] = x;
    __syncthreads();
    #pragma unroll
    for (int off = 1; off < 256; off <<= 1) {
        int v = (tid >= off) ? sm[tid - off] : 0;
        __syncthreads();
        sm[tid] += v;
        __syncthreads();
    }
    if (i < n1) g_ptr[i] = sm[tid] - x;
    if (tid == 255) g_part[blockIdx.x] = sm[255];
}

__global__ void kScan2(int nb) {
    __shared__ int sm[256];
    int tid = threadIdx.x;
    int x = (tid < nb) ? g_part[tid] : 0;
    sm[tid] = x;
    __syncthreads();
    #pragma unroll
    for (int off = 1; off < 256; off <<= 1) {
        int v = (tid >= off) ? sm[tid - off] : 0;
        __syncthreads();
        sm[tid] += v;
        __syncthreads();
    }
    g_pscan[tid] = sm[tid] - x;
}

__global__ void kScan3(int n1) {
    int i = blockIdx.x * blockDim.x + threadIdx.x;
    if (i < n1) {
        int v = g_ptr[i] + g_pscan[i >> 8];
        g_ptr[i] = v;
        if (i < n1 - 1) {
            g_cursor[i] = v;
            g_dinv[i] = rsqrtf(g_deg[i]);
        }
    }
}

__global__ void k_place(const int* __restrict__ row, const int* __restrict__ col,
                        const float* __restrict__ ew, int E) {
    int e = blockIdx.x * blockDim.x + threadIdx.x;
    if (e >= E) return;
    int c = col[e];
    int r = row[e];
    float w = ew[e];
    int slot = atomicAdd(&g_cursor[c], 1);
    g_csr_r[slot] = r;
    g_csr_w[slot] = w;
    g_csr_c[slot] = g_dinv[r] * w * g_dinv[c];
}

__global__ void k_tt_partial(const float* __restrict__ t, const float* __restrict__ tew) {
    int j = threadIdx.x;
    int k0 = blockIdx.x * 16;
    float acc = 0.f;
    #pragma unroll
    for (int k = 0; k < 16; k++) acc += lrelu(t[k0 + k], 0.01f) * tew[(k0 + k) * COUT + j];
    atomicAdd(&g_btt[j], acc);
}

// ---------------- tf32 tensor-core GEMM: [n,K] @ [K,128] ---------------------
template <int K, int BIAS, int OUTH, int GN0, int AL>
__global__ __launch_bounds__(256, 2)
void k_gemm_tc(const float* __restrict__ A, const float* __restrict__ W,
               const float* __restrict__ bias, float* __restrict__ out,
               __half* __restrict__ outh, const float* __restrict__ gnw,
               const float* __restrict__ gnb, const float* __restrict__ asrc,
               const float* __restrict__ adst, int n) {
    extern __shared__ unsigned smemu[];
    unsigned* Ws = smemu;              // [K][136]
    unsigned* As = smemu + K * 136;    // [128][20]
    int tid = threadIdx.x;
    for (int i = tid; i < K * 128; i += 256) {
        int k = i >> 7, j = i & 127;
        Ws[k * 136 + j] = f2tf32(W[i]);
    }
    int lane = tid & 31, w = tid >> 5;
    int wm = (w & 3) * 32;
    int wn = (w >> 2) * 64;
    int r = lane >> 2, q = lane & 3;
    int arow = tid >> 1;
    int acol = (tid & 1) * 8;
    int tiles = (n + 127) >> 7;

    float asr[2][8], adr[2][8];
    int hbase = wn >> 5;
    if (AL) {
        #pragma unroll
        for (int hh = 0; hh < 2; hh++)
            #pragma unroll
            for (int j = 0; j < 4; j++)
                #pragma unroll
                for (int i2 = 0; i2 < 2; i2++) {
                    int idx = (hbase + hh) * 32 + j * 8 + 2 * q + i2;
                    asr[hh][j * 2 + i2] = __ldg(asrc + idx);
                    adr[hh][j * 2 + i2] = __ldg(adst + idx);
                }
    }

    for (int tile = blockIdx.x; tile < tiles; tile += gridDim.x) {
        int m0 = tile << 7;
        float c[2][8][4];
        #pragma unroll
        for (int mt = 0; mt < 2; mt++)
            #pragma unroll
            for (int nt = 0; nt < 8; nt++)
                #pragma unroll
                for (int i = 0; i < 4; i++) c[mt][nt][i] = 0.f;

        for (int k0 = 0; k0 < K; k0 += 16) {
            __syncthreads();
            {
                int grow = m0 + arow;
                float4 v0 = make_float4(0.f,0.f,0.f,0.f), v1 = v0;
                if (grow < n) {
                    const float* ap = A + (size_t)grow * K + k0 + acol;
                    v0 = *(const float4*)ap;
                    v1 = *(const float4*)(ap + 4);
                }
                float v[8] = {v0.x, v0.y, v0.z, v0.w, v1.x, v1.y, v1.z, v1.w};
                if (GN0) {
                    float s = 0.f, ss = 0.f;
                    #pragma unroll
                    for (int i = 0; i < 8; i++) { s += v[i]; ss += v[i] * v[i]; }
                    float mean = s * 0.125f;
                    float var  = ss * 0.125f - mean * mean;
                    float inv  = rsqrtf(var + 1e-5f);
                    int gb = k0 + acol;
                    #pragma unroll
                    for (int i = 0; i < 8; i++)
                        v[i] = lrelu((v[i] - mean) * inv * __ldg(gnw + gb + i)
                                     + __ldg(gnb + gb + i), 0.01f);
                }
                unsigned* d = As + arow * 20 + acol;
                #pragma unroll
                for (int i = 0; i < 8; i++) d[i] = f2tf32(v[i]);
            }
            __syncthreads();
            #pragma unroll
            for (int kk = 0; kk < 16; kk += 8) {
                unsigned a[2][4];
                #pragma unroll
                for (int mt = 0; mt < 2; mt++) {
                    const unsigned* ap = As + (wm + mt * 16 + r) * 20 + kk + q;
                    a[mt][0] = ap[0];
                    a[mt][1] = ap[8 * 20];
                    a[mt][2] = ap[4];
                    a[mt][3] = ap[8 * 20 + 4];
                }
                #pragma unroll
                for (int nt = 0; nt < 8; nt++) {
                    unsigned b[2];
                    const unsigned* bp = Ws + (k0 + kk + q) * 136 + wn + nt * 8 + r;
                    b[0] = bp[0];
                    b[1] = bp[4 * 136];
                    mma_tf32(c[0][nt], a[0], b);
                    mma_tf32(c[1][nt], a[1], b);
                }
            }
        }
        #pragma unroll
        for (int mt = 0; mt < 2; mt++) {
            #pragma unroll
            for (int rr = 0; rr < 2; rr++) {
                int m = m0 + wm + mt * 16 + r + rr * 8;
                if (m < n) {
                    #pragma unroll
                    for (int nt = 0; nt < 8; nt++) {
                        int col = wn + nt * 8 + 2 * q;
                        float v0 = c[mt][nt][rr * 2 + 0];
                        float v1 = c[mt][nt][rr * 2 + 1];
                        if (BIAS) { v0 += bias[col]; v1 += bias[col + 1]; }
                        if (OUTH) {
                            *(__half2*)(outh + (size_t)m * 128 + col) = __floats2half2_rn(v0, v1);
                        } else {
                            *(float2*)(out + (size_t)m * 128 + col) = make_float2(v0, v1);
                        }
                    }
                }
                if (AL) {
                    float sA0 = 0.f, sA1 = 0.f, sD0 = 0.f, sD1 = 0.f;
                    #pragma unroll
                    for (int j = 0; j < 4; j++)
                        #pragma unroll
                        for (int i2 = 0; i2 < 2; i2++) {
                            float c0 = c[mt][j][rr * 2 + i2];
                            float c1 = c[mt][4 + j][rr * 2 + i2];
                            sA0 += c0 * asr[0][j * 2 + i2];
                            sD0 += c0 * adr[0][j * 2 + i2];
                            sA1 += c1 * asr[1][j * 2 + i2];
                            sD1 += c1 * adr[1][j * 2 + i2];
                        }
                    sA0 += __shfl_xor_sync(0xffffffffu, sA0, 1);
                    sA0 += __shfl_xor_sync(0xffffffffu, sA0, 2);
                    sA1 += __shfl_xor_sync(0xffffffffu, sA1, 1);
                    sA1 += __shfl_xor_sync(0xffffffffu, sA1, 2);
                    sD0 += __shfl_xor_sync(0xffffffffu, sD0, 1);
                    sD0 += __shfl_xor_sync(0xffffffffu, sD0, 2);
                    sD1 += __shfl_xor_sync(0xffffffffu, sD1, 1);
                    sD1 += __shfl_xor_sync(0xffffffffu, sD1, 2);
                    if (q == 0 && m < n) {
                        g_als[m * 4 + hbase]     = sA0;
                        g_als[m * 4 + hbase + 1] = sA1;
                        g_ald[m * 4 + hbase]     = sD0;
                        g_ald[m * 4 + hbase + 1] = sD1;
                    }
                }
            }
        }
    }
}

// ---------------- GCN conv (fp16 gather) + fused GN + LeakyReLU --------------
template <int BASEVEC>
__global__ void k_conv(const __half* __restrict__ srch, const float* __restrict__ basep,
                       float* __restrict__ dst,
                       const float* __restrict__ gnw, const float* __restrict__ gnb, int n) {
    int gw = (blockIdx.x * blockDim.x + threadIdx.x) >> 5;
    int lane = threadIdx.x & 31;
    if (gw >= n) return;
    int c = gw;
    int beg = g_ptr[c], end = g_ptr[c + 1];
    float dc = g_dinv[c];
    float4 base = BASEVEC ? *(const float4*)(g_btt + lane * 4)
                          : *(const float4*)(basep + (size_t)c * 128 + lane * 4);
    float d2 = dc * dc;
    float4 acc;
    {
        float2 raw = *(const float2*)(srch + (size_t)c * 128 + lane * 4);
        __half2* hp = (__half2*)&raw;
        float2 lo = __half22float2(hp[0]), hi = __half22float2(hp[1]);
        acc.x = base.x + d2 * lo.x; acc.y = base.y + d2 * lo.y;
        acc.z = base.z + d2 * hi.x; acc.w = base.w + d2 * hi.y;
    }
    for (int b0 = beg; b0 < end; b0 += 32) {
        int cnt = min(32, end - b0);
        int ridx = 0; float cw = 0.f;
        if (lane < cnt) { ridx = g_csr_r[b0 + lane]; cw = g_csr_c[b0 + lane]; }
        for (int j = 0; j < cnt; j++) {
            int r = __shfl_sync(0xffffffffu, ridx, j);
            float coef = __shfl_sync(0xffffffffu, cw, j);
            float2 raw = *(const float2*)(srch + (size_t)r * 128 + lane * 4);
            __half2* hp = (__half2*)&raw;
            float2 lo = __half22float2(hp[0]), hi = __half22float2(hp[1]);
            acc.x += coef * lo.x; acc.y += coef * lo.y;
            acc.z += coef * hi.x; acc.w += coef * hi.y;
        }
    }
    float s  = acc.x + acc.y + acc.z + acc.w;
    float ss = acc.x * acc.x + acc.y * acc.y + acc.z * acc.z + acc.w * acc.w;
    s  += __shfl_xor_sync(0xffffffffu, s, 1);  ss += __shfl_xor_sync(0xffffffffu, ss, 1);
    s  += __shfl_xor_sync(0xffffffffu, s, 2);  ss += __shfl_xor_sync(0xffffffffu, ss, 2);
    float mean = s * (1.f / 16.f);
    float var  = ss * (1.f / 16.f) - mean * mean;
    float inv  = rsqrtf(var + 1e-5f);
    float4 wv = *(const float4*)(gnw + lane * 4);
    float4 bv = *(const float4*)(gnb + lane * 4);
    float4 o;
    o.x = lrelu((acc.x - mean) * inv * wv.x + bv.x, 0.01f);
    o.y = lrelu((acc.y - mean) * inv * wv.y + bv.y, 0.01f);
    o.z = lrelu((acc.z - mean) * inv * wv.z + bv.z, 0.01f);
    o.w = lrelu((acc.w - mean) * inv * wv.w + bv.w, 0.01f);
    *(float4*)(dst + (size_t)c * 128 + lane * 4) = o;
}

// ---------------- fused GAT: warp-per-node, SINGLE-PASS flash softmax --------
// Online (m, t, acc) with running rescale; als rows prefetched per 32-edge
// batch into lane registers (full MLP) and distributed via shfl — the random
// gather never sits on the softmax dependency chain.
__global__ __launch_bounds__(256)
void k_attn(const float* __restrict__ aedge, const float* __restrict__ ba,
            float* __restrict__ out, int n) {
    int gw = (blockIdx.x * blockDim.x + threadIdx.x) >> 5;
    int lane = threadIdx.x & 31;
    if (gw >= n) return;
    int c = gw;
    int beg = g_ptr[c], end = g_ptr[c + 1];
    int h = lane >> 3;
    float aeh = __ldg(aedge + h);
    float adh = __ldg(g_ald + c * 4 + h);
    float ash = __ldg(g_als + c * 4 + h);
    float fill = decf(g_fill);
    // self term initializes the online state
    float m = lrelu(ash + adh + aeh * fill, 0.2f);
    float tsum = 1.f;
    float4 acc;
    {
        float2 raw = *(const float2*)(g_hah + (size_t)c * 128 + lane * 4);
        __half2* hp = (__half2*)&raw;
        float2 lo = __half22float2(hp[0]), hi = __half22float2(hp[1]);
        acc.x = lo.x; acc.y = lo.y; acc.z = hi.x; acc.w = hi.y;
    }
    for (int b0 = beg; b0 < end; b0 += 32) {
        int cnt = min(32, end - b0);
        int ridx = 0; float wreg = 0.f;
        float4 a4 = make_float4(0.f, 0.f, 0.f, 0.f);
        if (lane < cnt) {
            ridx = g_csr_r[b0 + lane];
            wreg = g_csr_w[b0 + lane];
            a4 = *(const float4*)(g_als + ridx * 4);   // prefetch, MLP=32
        }
        for (int j = 0; j < cnt; j++) {
            int r    = __shfl_sync(0xffffffffu, ridx, j);
            float w  = __shfl_sync(0xffffffffu, wreg, j);
            float ax = __shfl_sync(0xffffffffu, a4.x, j);
            float ay = __shfl_sync(0xffffffffu, a4.y, j);
            float az = __shfl_sync(0xffffffffu, a4.z, j);
            float aw = __shfl_sync(0xffffffffu, a4.w, j);
            float asr = (h == 0) ? ax : (h == 1) ? ay : (h == 2) ? az : aw;
            float l = lrelu(asr + adh + aeh * w, 0.2f);
            float nm = fmaxf(m, l);
            float sc = __expf(m - nm);
            float e  = __expf(l - nm);
            m = nm;
            tsum = tsum * sc + e;
            float2 raw = *(const float2*)(g_hah + (size_t)r * 128 + lane * 4);
            __half2* hp = (__half2*)&raw;
            float2 lo = __half22float2(hp[0]), hi = __half22float2(hp[1]);
            acc.x = acc.x * sc + e * lo.x;
            acc.y = acc.y * sc + e * lo.y;
            acc.z = acc.z * sc + e * hi.x;
            acc.w = acc.w * sc + e * hi.y;
        }
    }
    float rs = 1.f / (tsum + 1e-16f);
    float4 bav = *(const float4*)(ba + lane * 4);
    float4 o;
    o.x = bav.x + acc.x * rs;
    o.y = bav.y + acc.y * rs;
    o.z = bav.z + acc.z * rs;
    o.w = bav.w + acc.w * rs;
    *(float4*)(out + (size_t)c * 128 + lane * 4) = o;
}

// ---------------- launch -----------------------------------------------------
extern "C" void kernel_launch(void* const* d_in, const int* in_sizes, int n_in,
                              void* d_out, int out_size) {
    const float* x    = (const float*)d_in[0];
    const float* t    = (const float*)d_in[1];
    const int*   ei   = (const int*)  d_in[2];
    const float* ew   = (const float*)d_in[3];
    const float* gn0w = (const float*)d_in[4];
    const float* gn0b = (const float*)d_in[5];
    const float* W1   = (const float*)d_in[6];
    const float* b1   = (const float*)d_in[7];
    const float* gn1w = (const float*)d_in[8];
    const float* gn1b = (const float*)d_in[9];
    const float* W2   = (const float*)d_in[10];
    const float* b2   = (const float*)d_in[11];
    const float* Wres = (const float*)d_in[12];
    const float* tew  = (const float*)d_in[13];
    const float* teb  = (const float*)d_in[14];
    const float* gn2w = (const float*)d_in[15];
    const float* gn2b = (const float*)d_in[16];
    const float* Wa   = (const float*)d_in[17];
    const float* asrc = (const float*)d_in[18];
    const float* adst = (const float*)d_in[19];
    const float* aedg = (const float*)d_in[20];
    const float* ba   = (const float*)d_in[21];

    int n = in_sizes[0] / CIN;
    int E = in_sizes[3];
    const int* row  = ei;
    const int* colp = ei + E;
    float* out = (float*)d_out;

    const int SM64  = (64 * 136 + 128 * 20) * 4;
    const int SM128 = (128 * 136 + 128 * 20) * 4;

    static cudaStream_t s1 = nullptr, s2 = nullptr;
    static cudaEvent_t evInit = nullptr, evCSR = nullptr, evAux = nullptr;
    if (!s1) {
        cudaStreamCreateWithFlags(&s1, cudaStreamNonBlocking);
        cudaStreamCreateWithFlags(&s2, cudaStreamNonBlocking);
        cudaEventCreateWithFlags(&evInit, cudaEventDisableTiming);
        cudaEventCreateWithFlags(&evCSR,  cudaEventDisableTiming);
        cudaEventCreateWithFlags(&evAux,  cudaEventDisableTiming);
        cudaFuncSetAttribute(k_gemm_tc<CIN, 0, 1, 1, 0>,  cudaFuncAttributeMaxDynamicSharedMemorySize, SM64);
        cudaFuncSetAttribute(k_gemm_tc<CIN, 1, 0, 0, 0>,  cudaFuncAttributeMaxDynamicSharedMemorySize, SM64);
        cudaFuncSetAttribute(k_gemm_tc<COUT, 0, 1, 0, 0>, cudaFuncAttributeMaxDynamicSharedMemorySize, SM128);
        cudaFuncSetAttribute(k_gemm_tc<COUT, 0, 1, 0, 1>, cudaFuncAttributeMaxDynamicSharedMemorySize, SM128);
    }

    float *p_a128, *p_res;
    __half *p_xwh, *p_hah;
    cudaGetSymbolAddress((void**)&p_xwh,  g_xwh);
    cudaGetSymbolAddress((void**)&p_hah,  g_hah);
    cudaGetSymbolAddress((void**)&p_a128, g_a128);
    cudaGetSymbolAddress((void**)&p_res,  g_res);

    const int T = 256;
    int n1   = n + 1;
    int gN   = (n + T - 1) / T;
    int gE   = (E + T - 1) / T;
    int gNW  = (n * 32 + T - 1) / T;
    int gSC  = (n1 + 255) / 256;
    const int GG = 296;

    k_init<<<gN, T>>>(teb, b1, n);
    cudaEventRecord(evInit, 0);

    // s1: CSR build
    cudaStreamWaitEvent(s1, evInit, 0);
    k_count<<<gE, T, 0, s1>>>(colp, ew, E);
    kScan1<<<gSC, 256, 0, s1>>>(n1);
    kScan2<<<1, 256, 0, s1>>>(gSC);
    kScan3<<<gSC, 256, 0, s1>>>(n1);
    k_place<<<gE, T, 0, s1>>>(row, colp, ew, E);
    cudaEventRecord(evCSR, s1);

    // s2: residual GEMM + time embed
    cudaStreamWaitEvent(s2, evInit, 0);
    k_gemm_tc<CIN, 1, 0, 0, 0><<<GG, 256, SM64, s2>>>(x, Wres, b2, p_res, nullptr,
                                                      nullptr, nullptr, nullptr, nullptr, n);
    k_tt_partial<<<32, 128, 0, s2>>>(t, tew);
    cudaEventRecord(evAux, s2);

    // main chain
    k_gemm_tc<CIN, 0, 1, 1, 0><<<GG, 256, SM64>>>(x, W1, nullptr, nullptr, p_xwh,
                                                  gn0w, gn0b, nullptr, nullptr, n);
    cudaStreamWaitEvent(0, evCSR, 0);
    cudaStreamWaitEvent(0, evAux, 0);
    k_conv<1><<<gNW, T>>>(p_xwh, nullptr, p_a128, gn1w, gn1b, n);

    k_gemm_tc<COUT, 0, 1, 0, 0><<<GG, 256, SM128>>>(p_a128, W2, nullptr, nullptr, p_xwh,
                                                    nullptr, nullptr, nullptr, nullptr, n);
    k_conv<0><<<gNW, T>>>(p_xwh, p_res, p_a128, gn2w, gn2b, n);

    k_gemm_tc<COUT, 0, 1, 0, 1><<<GG, 256, SM128>>>(p_a128, Wa, nullptr, nullptr, p_hah,
                                                    nullptr, nullptr, asrc, adst, n);
    k_attn<<<gNW, T>>>(aedg, ba, out, n);
}